// round 1
// baseline (speedup 1.0000x reference)
#include <cuda_runtime.h>
#include <math.h>

#define CC 31
#define HO 256
#define WO 256
#define NPIX (HO*WO)          // 65536
#define HI 128
#define WI 128

// ---------------- static device scratch (no allocations allowed) ----------------
__device__ float d_fea0[CC*NPIX];          // bilinear-warped input (31,256,256)
__device__ float d_o[CC*NPIX];             // conv output + residual
__device__ float d_Ed[4*258*258*32];       // shell intermediate: depth slabs d'={-2,-1,31,32}
__device__ float d_Ey[2*31*258*32];        // shell: y'={-1,256}, d' in [0,30], x' in [-1,256]
__device__ float d_Ex[2*31*256*32];        // shell: x'={-1,256}, d' in [0,30], y in [0,255]
__device__ float d_wem[32*45];             // rsum-mixed expand weights  [k][dz*9+dy*3+dx]
__device__ float d_wcm[32*45];             // rsum-mixed compress weights
__device__ float d_wcmT[45*32];            // transposed compress weights [tap][k]
__device__ float d_g[225];                 // composed 9x5x5 kernel [sz*25+sy*5+sx]
__device__ float d_offp[4][2];             // per-parity offsets (p = (i&1)*2 | (j&1))
__device__ float d_r2p[4][4];              // per-parity routing2 (sigmoid)
__device__ float d_Mp[4*961];              // per-parity 31x31 mixing matrices

// ============================ k0: all scalar precompute ============================
__global__ void k0_precompute(
    const float* __restrict__ WE,  // (4,32,1,5,3,3)
    const float* __restrict__ WC,  // (4,1,32,5,3,3)
    const float* __restrict__ W2,  // (4,31,31,1,1)
    const float* __restrict__ bw1, const float* __restrict__ bb1,   // (64,3),(64)
    const float* __restrict__ bw2, const float* __restrict__ bb2,   // (64,64),(64)
    const float* __restrict__ r2w, const float* __restrict__ r2b,   // (4,64),(4)
    const float* __restrict__ ow,  const float* __restrict__ ob,    // (2,64),(2)
    const float* __restrict__ l1w, const float* __restrict__ l1b,   // (64,2),(64)
    const float* __restrict__ l2w, const float* __restrict__ l2b)   // (4,64),(4)
{
    __shared__ float rsum_s[4];
    __shared__ float e1s[4][64];
    __shared__ float e2s[4][64];
    __shared__ float r2s[4][4];
    int tid = threadIdx.x;   // 256 threads

    // ---- routing weight sum (scale=2 -> inp2 rows [0.5,-0.25],[0.5,0.25]) ----
    if (tid == 0) {
        float rs[4] = {0.f,0.f,0.f,0.f};
        for (int r = 0; r < 2; r++) {
            float chr = r ? 0.25f : -0.25f;
            float h1[64];
            for (int o = 0; o < 64; o++) {
                float a = l1w[o*2+0]*0.5f + l1w[o*2+1]*chr + l1b[o];
                h1[o] = a > 0.f ? a : 0.f;
            }
            float lg[4]; float m = -1e30f;
            for (int e = 0; e < 4; e++) {
                float a = l2b[e];
                for (int o = 0; o < 64; o++) a += l2w[e*64+o]*h1[o];
                lg[e] = a; if (a > m) m = a;
            }
            float s = 0.f;
            for (int e = 0; e < 4; e++) { lg[e] = expf(lg[e]-m); s += lg[e]; }
            for (int e = 0; e < 4; e++) rs[e] += lg[e]/s;
        }
        for (int e = 0; e < 4; e++) rsum_s[e] = rs[e];
    }

    // ---- per-parity MLP layer1 (4 combos x 64 units = 256 threads) ----
    {
        int p = tid >> 6, o = tid & 63;
        float ch = (p & 2) ? 0.25f : -0.25f;   // row parity
        float cw = (p & 1) ? 0.25f : -0.25f;   // col parity
        float a = bw1[o*3+0]*0.5f + bw1[o*3+1]*ch + bw1[o*3+2]*cw + bb1[o];
        e1s[p][o] = a > 0.f ? a : 0.f;
    }
    __syncthreads();
    {
        int p = tid >> 6, o = tid & 63;
        float a = bb2[o];
        for (int i = 0; i < 64; i++) a += bw2[o*64+i]*e1s[p][i];
        e2s[p][o] = a > 0.f ? a : 0.f;
    }
    __syncthreads();

    // ---- heads: offsets (2) + routing2 (4) per parity ----
    if (tid < 24) {
        int p = tid / 6, u = tid % 6;
        if (u < 2) {
            float a = ob[u];
            for (int i = 0; i < 64; i++) a += ow[u*64+i]*e2s[p][i];
            d_offp[p][u] = a;
        } else {
            int e = u - 2;
            float a = r2b[e];
            for (int i = 0; i < 64; i++) a += r2w[e*64+i]*e2s[p][i];
            float sg = 1.f/(1.f+expf(-a));
            r2s[p][e] = sg; d_r2p[p][e] = sg;
        }
    }

    // ---- rsum-mixed conv weights ----
    for (int idx = tid; idx < 32*45; idx += 256) {
        int t = idx % 45, k = idx / 45;
        float a = 0.f, b = 0.f;
        for (int e = 0; e < 4; e++) {
            a += rsum_s[e]*WE[e*1440 + idx];
            b += rsum_s[e]*WC[e*1440 + idx];
        }
        d_wem[idx] = a; d_wcm[idx] = b; d_wcmT[t*32 + k] = b;
    }
    __syncthreads();   // orders global writes within block + r2s ready

    // ---- composed 9x5x5 kernel g ----
    for (int s = tid; s < 225; s += 256) {
        int sz = s/25, sy = (s%25)/5, sx = s%5;
        int qzl = sz-4 > 0 ? sz-4 : 0, qzh = sz < 4 ? sz : 4;
        int qyl = sy-2 > 0 ? sy-2 : 0, qyh = sy < 2 ? sy : 2;
        int qxl = sx-2 > 0 ? sx-2 : 0, qxh = sx < 2 ? sx : 2;
        float acc = 0.f;
        for (int k = 0; k < 32; k++) {
            const float* wc_k = d_wcm + k*45;
            const float* we_k = d_wem + k*45;
            for (int qz = qzl; qz <= qzh; qz++)
            for (int qy = qyl; qy <= qyh; qy++)
            for (int qx = qxl; qx <= qxh; qx++) {
                int rz = sz-qz, ry = sy-qy, rx = sx-qx;
                acc += wc_k[qz*9+qy*3+qx]*we_k[rz*9+ry*3+rx];
            }
        }
        d_g[s] = acc;
    }

    // ---- per-parity mixing matrices Mp[p][i][j] = sum_e r2[p][e]*W2[e][i][j] ----
    for (int idx = tid; idx < 4*961; idx += 256) {
        int p = idx / 961, ij = idx % 961;
        float a = 0.f;
        for (int e = 0; e < 4; e++) a += r2s[p][e]*W2[e*961 + ij];
        d_Mp[idx] = a;
    }
}

// ============================ k1: bilinear warp -> fea0 ============================
__global__ void k1_fea0(const float* __restrict__ x)
{
    int idx = blockIdx.x*blockDim.x + threadIdx.x;
    if (idx >= NPIX) return;
    int i = idx >> 8, j = idx & 255;
    int p = ((i & 1) << 1) | (j & 1);
    float ix = (j + 0.5f)*0.5f - 0.5f + d_offp[p][0];
    float iy = (i + 0.5f)*0.5f - 0.5f + d_offp[p][1];
    float x0f = floorf(ix), y0f = floorf(iy);
    float wx1 = ix - x0f, wy1 = iy - y0f;
    int x0 = (int)x0f, y0 = (int)y0f;
    float vx0 = (x0   >= 0 && x0   <= WI-1) ? 1.f : 0.f;
    float vx1 = (x0+1 >= 0 && x0+1 <= WI-1) ? 1.f : 0.f;
    float vy0 = (y0   >= 0 && y0   <= HI-1) ? 1.f : 0.f;
    float vy1 = (y0+1 >= 0 && y0+1 <= HI-1) ? 1.f : 0.f;
    int xi0 = min(max(x0,   0), WI-1), xi1 = min(max(x0+1, 0), WI-1);
    int yi0 = min(max(y0,   0), HI-1), yi1 = min(max(y0+1, 0), HI-1);
    float w00 = (1.f-wy1)*(1.f-wx1)*vy0*vx0;
    float w01 = (1.f-wy1)*wx1*vy0*vx1;
    float w10 = wy1*(1.f-wx1)*vy1*vx0;
    float w11 = wy1*wx1*vy1*vx1;
    int b00 = yi0*WI + xi0, b01 = yi0*WI + xi1;
    int b10 = yi1*WI + xi0, b11 = yi1*WI + xi1;
    #pragma unroll 1
    for (int c = 0; c < CC; c++) {
        const float* xc = x + c*(HI*WI);
        d_fea0[c*NPIX + idx] = w00*xc[b00] + w01*xc[b01] + w10*xc[b10] + w11*xc[b11];
    }
}

// ============================ k2: fused 9x5x5 conv + residual ============================
// block (32,6): 32x6 output tile over all 31 depths; smem tile 31 x 10 x 36.
__global__ __launch_bounds__(192) void k2_conv()
{
    __shared__ float gs[225];
    __shared__ float tile[CC][10][36];
    int tx = threadIdx.x, ty = threadIdx.y;
    int tid = ty*32 + tx;
    int gx0 = blockIdx.x*32 - 2, gy0 = blockIdx.y*6 - 2;

    for (int t = tid; t < 225; t += 192) gs[t] = d_g[t];
    for (int t = tid; t < CC*360; t += 192) {
        int d = t / 360, r = t % 360, yy = r / 36, xx = r % 36;
        int gy = gy0 + yy, gx = gx0 + xx;
        float v = 0.f;
        if (gy >= 0 && gy < HO && gx >= 0 && gx < WO)
            v = d_fea0[d*NPIX + gy*WO + gx];
        tile[d][yy][xx] = v;
    }
    __syncthreads();

    int oy = blockIdx.y*6 + ty, ox = blockIdx.x*32 + tx;
    if (oy >= HO) return;

    float acc[CC];
    #pragma unroll
    for (int d = 0; d < CC; d++) acc[d] = tile[d][ty+2][tx+2];   // residual (+fea)

    for (int sy = 0; sy < 5; sy++) {
        for (int sx = 0; sx < 5; sx++) {
            float v[CC];
            #pragma unroll
            for (int d = 0; d < CC; d++) v[d] = tile[d][ty+sy][tx+sx];
            #pragma unroll
            for (int sz = 0; sz < 9; sz++) {
                float gv = gs[sz*25 + sy*5 + sx];
                #pragma unroll
                for (int d = 0; d < CC; d++) {
                    int src = d + sz - 4;
                    if (src >= 0 && src < CC) acc[d] += gv * v[src];
                }
            }
        }
    }
    int out = oy*WO + ox;
    #pragma unroll
    for (int d = 0; d < CC; d++) d_o[d*NPIX + out] = acc[d];
}

// ============================ k3: shell intermediate Ihat_k ============================
__device__ __forceinline__ void eval_I(int dp, int yp, int xp,
                                       const float* __restrict__ wem_s,
                                       float* __restrict__ outp)
{
    float acc[32];
    #pragma unroll
    for (int k = 0; k < 32; k++) acc[k] = 0.f;
    int rzl = 2 - dp;  if (rzl < 0) rzl = 0;
    int rzh = 32 - dp; if (rzh > 4) rzh = 4;
    for (int rz = rzl; rz <= rzh; rz++) {
        const float* fbase = d_fea0 + (dp + rz - 2)*NPIX;
        for (int ry = 0; ry < 3; ry++) {
            int fy = yp + ry - 1;
            if (fy < 0 || fy > HO-1) continue;
            for (int rx = 0; rx < 3; rx++) {
                int fx = xp + rx - 1;
                if (fx < 0 || fx > WO-1) continue;
                float f = fbase[fy*WO + fx];
                int t = rz*9 + ry*3 + rx;
                #pragma unroll
                for (int k = 0; k < 32; k++) acc[k] += wem_s[k*45 + t]*f;
            }
        }
    }
    #pragma unroll
    for (int k = 0; k < 32; k++) outp[k] = acc[k];
}

#define N_ED (4*258*258)
#define N_EY (2*31*258)
#define N_EX (2*31*256)

__global__ void k3_shell()
{
    __shared__ float wem_s[32*45];
    int tid = threadIdx.x;
    for (int t = tid; t < 32*45; t += 256) wem_s[t] = d_wem[t];
    __syncthreads();

    int idx = blockIdx.x*256 + tid;
    if (idx < N_ED) {
        int a = idx / (258*258), r = idx % (258*258);
        int yy = r / 258, xx = r % 258;
        int dp = (a < 2) ? a - 2 : a + 29;       // -2,-1,31,32
        eval_I(dp, yy-1, xx-1, wem_s, d_Ed + (size_t)idx*32);
        return;
    }
    idx -= N_ED;
    if (idx < N_EY) {
        int b = idx / (31*258), r = idx % (31*258);
        int dp = r / 258, xx = r % 258;
        int yp = b ? HO : -1;
        eval_I(dp, yp, xx-1, wem_s, d_Ey + (size_t)idx*32);
        return;
    }
    idx -= N_EY;
    if (idx < N_EX) {
        int b = idx / (31*256), r = idx % (31*256);
        int dp = r / 256, y = r % 256;
        int xp = b ? WO : -1;
        eval_I(dp, y, xp, wem_s, d_Ex + (size_t)idx*32);
    }
}

// ============================ k4: boundary correction gather ============================
__global__ void k4_corr()
{
    __shared__ float wct[45*32];
    int tid = threadIdx.x;
    for (int t = tid; t < 45*32; t += 256) wct[t] = d_wcmT[t];
    __syncthreads();

    int idx = blockIdx.x*256 + tid;
    if (idx >= CC*NPIX) return;
    int d = idx / NPIX, rp = idx % NPIX;
    int y = rp >> 8, x = rp & 255;
    if (d >= 2 && d <= 28 && y >= 1 && y <= 254 && x >= 1 && x <= 254) return;

    float corr = 0.f;
    for (int qz = 0; qz < 5; qz++) {
        int dp = d + qz - 2;
        bool dinv = (dp < 0) || (dp > 30);
        for (int qy = 0; qy < 3; qy++) {
            int yp = y + qy - 1;
            bool yinv = (yp < 0) || (yp > HO-1);
            for (int qx = 0; qx < 3; qx++) {
                int xp = x + qx - 1;
                bool xinv = (xp < 0) || (xp > WO-1);
                if (!(dinv || yinv || xinv)) continue;
                const float* Ep;
                if (dinv) {
                    int a = dp < 0 ? dp + 2 : dp - 29;
                    Ep = d_Ed + ((size_t)((a*258 + (yp+1))*258 + (xp+1)))*32;
                } else if (yinv) {
                    int b = yp < 0 ? 0 : 1;
                    Ep = d_Ey + ((size_t)((b*31 + dp)*258 + (xp+1)))*32;
                } else {
                    int b = xp < 0 ? 0 : 1;
                    Ep = d_Ex + ((size_t)((b*31 + dp)*256 + yp))*32;
                }
                const float* wq = wct + (qz*9 + qy*3 + qx)*32;
                float s = 0.f;
                #pragma unroll
                for (int k = 0; k < 32; k++) s += wq[k]*Ep[k];
                corr += s;
            }
        }
    }
    d_o[idx] -= corr;
}

// ============================ k5: per-pixel channel mix + fea0 ============================
__global__ void k5_mix(float* __restrict__ out)
{
    __shared__ float Mps[4*961];
    int tid = threadIdx.x;
    for (int t = tid; t < 4*961; t += 256) Mps[t] = d_Mp[t];
    __syncthreads();

    int pix = blockIdx.x*256 + tid;
    if (pix >= NPIX) return;
    int i = pix >> 8, j = pix & 255;
    const float* M = Mps + (((i & 1) << 1) | (j & 1))*961;

    float ov[CC];
    #pragma unroll
    for (int jj = 0; jj < CC; jj++) ov[jj] = d_o[jj*NPIX + pix];

    #pragma unroll 1
    for (int ii = 0; ii < CC; ii++) {
        float a = d_fea0[ii*NPIX + pix];
        const float* Mr = M + ii*31;
        #pragma unroll
        for (int jj = 0; jj < CC; jj++) a += Mr[jj]*ov[jj];
        out[ii*NPIX + pix] = a;
    }
}

// ============================ launch ============================
extern "C" void kernel_launch(void* const* d_in, const int* in_sizes, int n_in,
                              void* d_out, int out_size)
{
    const float* x   = (const float*)d_in[0];
    // d_in[1] = scale (always 2; parity tables assume it)
    const float* WE  = (const float*)d_in[2];
    const float* WC  = (const float*)d_in[3];
    const float* W2  = (const float*)d_in[4];
    const float* bw1 = (const float*)d_in[5];
    const float* bb1 = (const float*)d_in[6];
    const float* bw2 = (const float*)d_in[7];
    const float* bb2 = (const float*)d_in[8];
    const float* r2w = (const float*)d_in[9];
    const float* r2b = (const float*)d_in[10];
    const float* ow  = (const float*)d_in[11];
    const float* ob  = (const float*)d_in[12];
    const float* l1w = (const float*)d_in[13];
    const float* l1b = (const float*)d_in[14];
    const float* l2w = (const float*)d_in[15];
    const float* l2b = (const float*)d_in[16];
    float* out = (float*)d_out;

    k0_precompute<<<1, 256>>>(WE, WC, W2, bw1, bb1, bw2, bb2,
                              r2w, r2b, ow, ob, l1w, l1b, l2w, l2b);
    k1_fea0<<<NPIX/256, 256>>>(x);
    k2_conv<<<dim3(WO/32, (HO+5)/6), dim3(32, 6)>>>();
    int nshell = N_ED + N_EY + N_EX;
    k3_shell<<<(nshell + 255)/256, 256>>>();
    k4_corr<<<(CC*NPIX + 255)/256, 256>>>();
    k5_mix<<<NPIX/256, 256>>>(out);
}

// round 2
// speedup vs baseline: 13.2699x; 13.2699x over previous
#include <cuda_runtime.h>
#include <math.h>

#define CC 31
#define HO 256
#define WO 256
#define NPIX (HO*WO)          // 65536
#define HI 128
#define WI 128

// ---------------- static device scratch ----------------
__device__ float d_fea0[CC*NPIX];   // bilinear-warped input (31,256,256)
__device__ float d_o[CC*NPIX];      // conv output + residual
__device__ float d_wem[32*45];      // rsum-mixed expand weights  [k][dz*9+dy*3+dx]
__device__ float d_wcm[32*45];      // rsum-mixed compress weights
__device__ float d_gcls[5*3*3*225]; // 45 boundary-class composed 9x5x5 kernels
__device__ float d_offp[4][2];      // per-parity offsets (p = (i&1)*2 | (j&1))
__device__ float d_Mp[4*961];       // per-parity 31x31 mixing matrices

// class membership: zc: 0->d=0, 1->d=1, 2->interior, 3->d=29, 4->d=30
__device__ __forceinline__ bool inQz(int zc, int qz) {
    switch (zc) {
        case 0: return qz >= 2;
        case 1: return qz >= 1;
        case 2: return true;
        case 3: return qz <= 3;
        default: return qz <= 2;
    }
}
// yc/xc: 0->interior, 1->low edge (y=0), 2->high edge (y=255)
__device__ __forceinline__ bool inQ3(int c, int q) {
    return (c == 0) || (c == 1 ? q >= 1 : q <= 1);
}

// ============================ k0: all scalar precompute ============================
__global__ void k0_precompute(
    const float* __restrict__ WE,  // (4,32,1,5,3,3)
    const float* __restrict__ WC,  // (4,1,32,5,3,3)
    const float* __restrict__ W2,  // (4,31,31,1,1)
    const float* __restrict__ bw1, const float* __restrict__ bb1,   // (64,3),(64)
    const float* __restrict__ bw2, const float* __restrict__ bb2,   // (64,64),(64)
    const float* __restrict__ r2w, const float* __restrict__ r2b,   // (4,64),(4)
    const float* __restrict__ ow,  const float* __restrict__ ob,    // (2,64),(2)
    const float* __restrict__ l1w, const float* __restrict__ l1b,   // (64,2),(64)
    const float* __restrict__ l2w, const float* __restrict__ l2b)   // (4,64),(4)
{
    __shared__ float rsum_s[4];
    __shared__ float e1s[4][64];
    __shared__ float e2s[4][64];
    __shared__ float r2s[4][4];
    __shared__ float G2s[45*45];     // composed tap-pair matrix
    int tid = threadIdx.x;   // 256 threads

    // ---- routing weight sum (scale=2 -> inp2 rows [0.5,-0.25],[0.5,0.25]) ----
    if (tid == 0) {
        float rs[4] = {0.f,0.f,0.f,0.f};
        for (int r = 0; r < 2; r++) {
            float chr = r ? 0.25f : -0.25f;
            float h1[64];
            for (int o = 0; o < 64; o++) {
                float a = l1w[o*2+0]*0.5f + l1w[o*2+1]*chr + l1b[o];
                h1[o] = a > 0.f ? a : 0.f;
            }
            float lg[4]; float m = -1e30f;
            for (int e = 0; e < 4; e++) {
                float a = l2b[e];
                for (int o = 0; o < 64; o++) a += l2w[e*64+o]*h1[o];
                lg[e] = a; if (a > m) m = a;
            }
            float s = 0.f;
            for (int e = 0; e < 4; e++) { lg[e] = expf(lg[e]-m); s += lg[e]; }
            for (int e = 0; e < 4; e++) rs[e] += lg[e]/s;
        }
        for (int e = 0; e < 4; e++) rsum_s[e] = rs[e];
    }

    // ---- per-parity MLP layer1 (4 combos x 64 units = 256 threads) ----
    {
        int p = tid >> 6, o = tid & 63;
        float ch = (p & 2) ? 0.25f : -0.25f;   // row parity
        float cw = (p & 1) ? 0.25f : -0.25f;   // col parity
        float a = bw1[o*3+0]*0.5f + bw1[o*3+1]*ch + bw1[o*3+2]*cw + bb1[o];
        e1s[p][o] = a > 0.f ? a : 0.f;
    }
    __syncthreads();
    {
        int p = tid >> 6, o = tid & 63;
        float a = bb2[o];
        for (int i = 0; i < 64; i++) a += bw2[o*64+i]*e1s[p][i];
        e2s[p][o] = a > 0.f ? a : 0.f;
    }
    __syncthreads();

    // ---- heads: offsets (2) + routing2 (4) per parity ----
    if (tid < 24) {
        int p = tid / 6, u = tid % 6;
        if (u < 2) {
            float a = ob[u];
            for (int i = 0; i < 64; i++) a += ow[u*64+i]*e2s[p][i];
            d_offp[p][u] = a;
        } else {
            int e = u - 2;
            float a = r2b[e];
            for (int i = 0; i < 64; i++) a += r2w[e*64+i]*e2s[p][i];
            float sg = 1.f/(1.f+expf(-a));
            r2s[p][e] = sg;
        }
    }

    // ---- rsum-mixed conv weights ----
    for (int idx = tid; idx < 32*45; idx += 256) {
        float a = 0.f, b = 0.f;
        for (int e = 0; e < 4; e++) {
            a += rsum_s[e]*WE[e*1440 + idx];
            b += rsum_s[e]*WC[e*1440 + idx];
        }
        d_wem[idx] = a; d_wcm[idx] = b;
    }
    __syncthreads();   // d_wem/d_wcm visible within block; r2s ready

    // ---- G2[q][r] = sum_k wc_k[q] * we_k[r] ----
    for (int idx = tid; idx < 45*45; idx += 256) {
        int q = idx / 45, r = idx % 45;
        float acc = 0.f;
        for (int k = 0; k < 32; k++)
            acc += d_wcm[k*45+q]*d_wem[k*45+r];
        G2s[idx] = acc;
    }
    __syncthreads();

    // ---- 45 boundary-class composed kernels ----
    for (int e = tid; e < 45*225; e += 256) {
        int cls = e / 225, s = e % 225;
        int zc = cls / 9, yc = (cls % 9) / 3, xc = cls % 3;
        int sz = s / 25, sy = (s % 25) / 5, sx = s % 5;
        float acc = 0.f;
        for (int qz = 0; qz < 5; qz++) {
            if (!inQz(zc, qz)) continue;
            int rz = sz - qz; if (rz < 0 || rz > 4) continue;
            for (int qy = 0; qy < 3; qy++) {
                if (!inQ3(yc, qy)) continue;
                int ry = sy - qy; if (ry < 0 || ry > 2) continue;
                for (int qx = 0; qx < 3; qx++) {
                    if (!inQ3(xc, qx)) continue;
                    int rx = sx - qx; if (rx < 0 || rx > 2) continue;
                    acc += G2s[(qz*9+qy*3+qx)*45 + rz*9+ry*3+rx];
                }
            }
        }
        d_gcls[e] = acc;
    }

    // ---- per-parity mixing matrices Mp[p][i][j] = sum_e r2[p][e]*W2[e][i][j] ----
    for (int idx = tid; idx < 4*961; idx += 256) {
        int p = idx / 961, ij = idx % 961;
        float a = 0.f;
        for (int e = 0; e < 4; e++) a += r2s[p][e]*W2[e*961 + ij];
        d_Mp[idx] = a;
    }
}

// ============================ k1: bilinear warp -> fea0 ============================
__global__ void k1_fea0(const float* __restrict__ x)
{
    int idx = blockIdx.x*blockDim.x + threadIdx.x;
    if (idx >= NPIX) return;
    int i = idx >> 8, j = idx & 255;
    int p = ((i & 1) << 1) | (j & 1);
    float ix = (j + 0.5f)*0.5f - 0.5f + d_offp[p][0];
    float iy = (i + 0.5f)*0.5f - 0.5f + d_offp[p][1];
    float x0f = floorf(ix), y0f = floorf(iy);
    float wx1 = ix - x0f, wy1 = iy - y0f;
    int x0 = (int)x0f, y0 = (int)y0f;
    float vx0 = (x0   >= 0 && x0   <= WI-1) ? 1.f : 0.f;
    float vx1 = (x0+1 >= 0 && x0+1 <= WI-1) ? 1.f : 0.f;
    float vy0 = (y0   >= 0 && y0   <= HI-1) ? 1.f : 0.f;
    float vy1 = (y0+1 >= 0 && y0+1 <= HI-1) ? 1.f : 0.f;
    int xi0 = min(max(x0,   0), WI-1), xi1 = min(max(x0+1, 0), WI-1);
    int yi0 = min(max(y0,   0), HI-1), yi1 = min(max(y0+1, 0), HI-1);
    float w00 = (1.f-wy1)*(1.f-wx1)*vy0*vx0;
    float w01 = (1.f-wy1)*wx1*vy0*vx1;
    float w10 = wy1*(1.f-wx1)*vy1*vx0;
    float w11 = wy1*wx1*vy1*vx1;
    int b00 = yi0*WI + xi0, b01 = yi0*WI + xi1;
    int b10 = yi1*WI + xi0, b11 = yi1*WI + xi1;
    #pragma unroll 1
    for (int c = 0; c < CC; c++) {
        const float* xc = x + c*(HI*WI);
        d_fea0[c*NPIX + idx] = w00*xc[b00] + w01*xc[b01] + w10*xc[b10] + w11*xc[b11];
    }
}

// ============================ k2: exact fused conv (class kernels) + residual ============================
// block (32,6): 32x6 output tile over all 31 depths; smem tile 31 x 10 x 36.
__global__ __launch_bounds__(192) void k2_conv()
{
    __shared__ float tile[CC][10][36];     // 44.6 KB
    int tx = threadIdx.x, ty = threadIdx.y;
    int tid = ty*32 + tx;
    int gx0 = blockIdx.x*32 - 2, gy0 = blockIdx.y*6 - 2;

    for (int t = tid; t < CC*360; t += 192) {
        int d = t / 360, r = t % 360, yy = r / 36, xx = r % 36;
        int gy = gy0 + yy, gx = gx0 + xx;
        float v = 0.f;
        if (gy >= 0 && gy < HO && gx >= 0 && gx < WO)
            v = d_fea0[d*NPIX + gy*WO + gx];
        tile[d][yy][xx] = v;
    }
    __syncthreads();

    int oy = blockIdx.y*6 + ty, ox = blockIdx.x*32 + tx;
    if (oy >= HO) return;

    int yc = (oy == 0) ? 1 : ((oy == HO-1) ? 2 : 0);
    int xc = (ox == 0) ? 1 : ((ox == WO-1) ? 2 : 0);
    const float* gY = d_gcls + (yc*3 + xc)*225;   // + zc*2025 selects z-class

    float acc[CC];
    #pragma unroll
    for (int d = 0; d < CC; d++) acc[d] = tile[d][ty+2][tx+2];   // residual (+fea)

    #pragma unroll 1
    for (int sy = 0; sy < 5; sy++) {
        #pragma unroll 1
        for (int sx = 0; sx < 5; sx++) {
            int t0 = sy*5 + sx;
            float v[CC];
            #pragma unroll
            for (int d = 0; d < CC; d++) v[d] = tile[d][ty+sy][tx+sx];

            // interior depths d=2..28 use z-interior class kernel (zc=2)
            #pragma unroll
            for (int sz = 0; sz < 9; sz++) {
                float gv = __ldg(&gY[2*2025 + sz*25 + t0]);
                #pragma unroll
                for (int d = 2; d <= 28; d++) {
                    int src = d + sz - 4;
                    if (src >= 0 && src < CC) acc[d] += gv * v[src];
                }
            }
            // d=0 (zc=0): valid sz 4..8, src=sz-4
            #pragma unroll
            for (int sz = 4; sz < 9; sz++)
                acc[0] += __ldg(&gY[0*2025 + sz*25 + t0]) * v[sz-4];
            // d=1 (zc=1): valid sz 3..8, src=sz-3
            #pragma unroll
            for (int sz = 3; sz < 9; sz++)
                acc[1] += __ldg(&gY[1*2025 + sz*25 + t0]) * v[sz-3];
            // d=29 (zc=3): valid sz 0..5, src=25+sz
            #pragma unroll
            for (int sz = 0; sz < 6; sz++)
                acc[29] += __ldg(&gY[3*2025 + sz*25 + t0]) * v[25+sz];
            // d=30 (zc=4): valid sz 0..4, src=26+sz
            #pragma unroll
            for (int sz = 0; sz < 5; sz++)
                acc[30] += __ldg(&gY[4*2025 + sz*25 + t0]) * v[26+sz];
        }
    }
    int out = oy*WO + ox;
    #pragma unroll
    for (int d = 0; d < CC; d++) d_o[d*NPIX + out] = acc[d];
}

// ============================ k5: per-pixel channel mix + fea0 ============================
__global__ void k5_mix(float* __restrict__ out)
{
    __shared__ float Mps[4*961];
    int tid = threadIdx.x;
    for (int t = tid; t < 4*961; t += 256) Mps[t] = d_Mp[t];
    __syncthreads();

    int pix = blockIdx.x*256 + tid;
    if (pix >= NPIX) return;
    int i = pix >> 8, j = pix & 255;
    const float* M = Mps + (((i & 1) << 1) | (j & 1))*961;

    float ov[CC];
    #pragma unroll
    for (int jj = 0; jj < CC; jj++) ov[jj] = d_o[jj*NPIX + pix];

    #pragma unroll 1
    for (int ii = 0; ii < CC; ii++) {
        float a = d_fea0[ii*NPIX + pix];
        const float* Mr = M + ii*31;
        #pragma unroll
        for (int jj = 0; jj < CC; jj++) a += Mr[jj]*ov[jj];
        out[ii*NPIX + pix] = a;
    }
}

// ============================ launch ============================
extern "C" void kernel_launch(void* const* d_in, const int* in_sizes, int n_in,
                              void* d_out, int out_size)
{
    const float* x   = (const float*)d_in[0];
    // d_in[1] = scale (always 2; parity tables assume it)
    const float* WE  = (const float*)d_in[2];
    const float* WC  = (const float*)d_in[3];
    const float* W2  = (const float*)d_in[4];
    const float* bw1 = (const float*)d_in[5];
    const float* bb1 = (const float*)d_in[6];
    const float* bw2 = (const float*)d_in[7];
    const float* bb2 = (const float*)d_in[8];
    const float* r2w = (const float*)d_in[9];
    const float* r2b = (const float*)d_in[10];
    const float* ow  = (const float*)d_in[11];
    const float* ob  = (const float*)d_in[12];
    const float* l1w = (const float*)d_in[13];
    const float* l1b = (const float*)d_in[14];
    const float* l2w = (const float*)d_in[15];
    const float* l2b = (const float*)d_in[16];
    float* out = (float*)d_out;

    k0_precompute<<<1, 256>>>(WE, WC, W2, bw1, bb1, bw2, bb2,
                              r2w, r2b, ow, ob, l1w, l1b, l2w, l2b);
    k1_fea0<<<NPIX/256, 256>>>(x);
    k2_conv<<<dim3(WO/32, (HO+5)/6), dim3(32, 6)>>>();
    k5_mix<<<NPIX/256, 256>>>(out);
}

// round 3
// speedup vs baseline: 15.5656x; 1.1730x over previous
#include <cuda_runtime.h>
#include <math.h>

#define CC 31
#define HO 256
#define WO 256
#define NPIX (HO*WO)          // 65536
#define HI 128
#define WI 128

// ---------------- static device scratch ----------------
__device__ float d_wem[32*45];      // rsum-mixed expand weights  [k][dz*9+dy*3+dx]
__device__ float d_wcm[32*45];      // rsum-mixed compress weights
__device__ float d_G2[45*45];       // composed tap-pair matrix
__device__ float d_gcls[5*3*3*225]; // 45 boundary-class composed 9x5x5 kernels
__device__ float d_offp[4][2];      // per-parity offsets (p = (i&1)*2 | (j&1))
__device__ float d_r2p[4][4];       // per-parity routing2 (sigmoid)
__device__ float d_Mp[4*961];       // per-parity 31x31 mixing matrices

// class membership: zc: 0->d=0, 1->d=1, 2->interior, 3->d=29, 4->d=30
__device__ __forceinline__ bool inQz(int zc, int qz) {
    switch (zc) {
        case 0: return qz >= 2;
        case 1: return qz >= 1;
        case 2: return true;
        case 3: return qz <= 3;
        default: return qz <= 2;
    }
}
// yc/xc: 0->interior, 1->low edge, 2->high edge
__device__ __forceinline__ bool inQ3(int c, int q) {
    return (c == 0) || (c == 1 ? q >= 1 : q <= 1);
}

// ============================ k0a: scalar precompute (1 block) ============================
__global__ void k0a_precompute(
    const float* __restrict__ WE,  // (4,32,1,5,3,3)
    const float* __restrict__ WC,  // (4,1,32,5,3,3)
    const float* __restrict__ bw1, const float* __restrict__ bb1,   // (64,3),(64)
    const float* __restrict__ bw2, const float* __restrict__ bb2,   // (64,64),(64)
    const float* __restrict__ r2w, const float* __restrict__ r2b,   // (4,64),(4)
    const float* __restrict__ ow,  const float* __restrict__ ob,    // (2,64),(2)
    const float* __restrict__ l1w, const float* __restrict__ l1b,   // (64,2),(64)
    const float* __restrict__ l2w, const float* __restrict__ l2b)   // (4,64),(4)
{
    __shared__ float rsum_s[4];
    __shared__ float e1s[4][64];
    __shared__ float e2s[4][64];
    int tid = threadIdx.x;   // 256 threads

    // ---- routing weight sum (scale=2 -> inp2 rows [0.5,-0.25],[0.5,0.25]) ----
    if (tid == 0) {
        float rs[4] = {0.f,0.f,0.f,0.f};
        for (int r = 0; r < 2; r++) {
            float chr = r ? 0.25f : -0.25f;
            float h1[64];
            for (int o = 0; o < 64; o++) {
                float a = l1w[o*2+0]*0.5f + l1w[o*2+1]*chr + l1b[o];
                h1[o] = a > 0.f ? a : 0.f;
            }
            float lg[4]; float m = -1e30f;
            for (int e = 0; e < 4; e++) {
                float a = l2b[e];
                for (int o = 0; o < 64; o++) a += l2w[e*64+o]*h1[o];
                lg[e] = a; if (a > m) m = a;
            }
            float s = 0.f;
            for (int e = 0; e < 4; e++) { lg[e] = expf(lg[e]-m); s += lg[e]; }
            for (int e = 0; e < 4; e++) rs[e] += lg[e]/s;
        }
        for (int e = 0; e < 4; e++) rsum_s[e] = rs[e];
    }

    // ---- per-parity MLP layer1 ----
    {
        int p = tid >> 6, o = tid & 63;
        float ch = (p & 2) ? 0.25f : -0.25f;
        float cw = (p & 1) ? 0.25f : -0.25f;
        float a = bw1[o*3+0]*0.5f + bw1[o*3+1]*ch + bw1[o*3+2]*cw + bb1[o];
        e1s[p][o] = a > 0.f ? a : 0.f;
    }
    __syncthreads();
    {
        int p = tid >> 6, o = tid & 63;
        float a = bb2[o];
        for (int i = 0; i < 64; i++) a += bw2[o*64+i]*e1s[p][i];
        e2s[p][o] = a > 0.f ? a : 0.f;
    }
    __syncthreads();

    // ---- heads: offsets (2) + routing2 (4) per parity ----
    if (tid < 24) {
        int p = tid / 6, u = tid % 6;
        if (u < 2) {
            float a = ob[u];
            for (int i = 0; i < 64; i++) a += ow[u*64+i]*e2s[p][i];
            d_offp[p][u] = a;
        } else {
            int e = u - 2;
            float a = r2b[e];
            for (int i = 0; i < 64; i++) a += r2w[e*64+i]*e2s[p][i];
            d_r2p[p][e] = 1.f/(1.f+expf(-a));
        }
    }

    // ---- rsum-mixed conv weights ----
    for (int idx = tid; idx < 32*45; idx += 256) {
        float a = 0.f, b = 0.f;
        for (int e = 0; e < 4; e++) {
            a += rsum_s[e]*WE[e*1440 + idx];
            b += rsum_s[e]*WC[e*1440 + idx];
        }
        d_wem[idx] = a; d_wcm[idx] = b;
    }
    __syncthreads();

    // ---- G2[q][r] = sum_k wc_k[q] * we_k[r] ----
    for (int idx = tid; idx < 45*45; idx += 256) {
        int q = idx / 45, r = idx % 45;
        float acc = 0.f;
        for (int k = 0; k < 32; k++)
            acc += d_wcm[k*45+q]*d_wem[k*45+r];
        d_G2[idx] = acc;
    }
}

// ============================ k0b: class kernels + mix matrices (49 blocks) ============================
__global__ void k0b_tables(const float* __restrict__ W2)   // (4,31,31,1,1)
{
    int tid = threadIdx.x;
    int bid = blockIdx.x;
    if (bid < 45) {
        __shared__ float G2s[45*45];
        for (int t = tid; t < 45*45; t += 256) G2s[t] = d_G2[t];
        __syncthreads();
        if (tid >= 225) return;
        int cls = bid;
        int zc = cls / 9, yc = (cls % 9) / 3, xc = cls % 3;
        int s = tid;
        int sz = s / 25, sy = (s % 25) / 5, sx = s % 5;
        float acc = 0.f;
        for (int qz = 0; qz < 5; qz++) {
            if (!inQz(zc, qz)) continue;
            int rz = sz - qz; if (rz < 0 || rz > 4) continue;
            for (int qy = 0; qy < 3; qy++) {
                if (!inQ3(yc, qy)) continue;
                int ry = sy - qy; if (ry < 0 || ry > 2) continue;
                for (int qx = 0; qx < 3; qx++) {
                    if (!inQ3(xc, qx)) continue;
                    int rx = sx - qx; if (rx < 0 || rx > 2) continue;
                    acc += G2s[(qz*9+qy*3+qx)*45 + rz*9+ry*3+rx];
                }
            }
        }
        d_gcls[cls*225 + s] = acc;
    } else {
        int p = bid - 45;
        float r0 = d_r2p[p][0], r1 = d_r2p[p][1], r2 = d_r2p[p][2], r3 = d_r2p[p][3];
        for (int ij = tid; ij < 961; ij += 256)
            d_Mp[p*961 + ij] = r0*W2[ij] + r1*W2[961 + ij] + r2*W2[2*961 + ij] + r3*W2[3*961 + ij];
    }
}

// ============================ fused: bilinear + exact conv + residual + mix ============================
// block (32,6): 32x6 output pixels, all 31 depths.
// dynamic smem: tile[31][10][36] | wcls[4][5*225] | Mps[4*961] | offs[8]
#define TILE_F (CC*10*36)
#define WCLS_F (4*5*225)
#define MPS_F  (4*961)
#define SMEM_F (TILE_F + WCLS_F + MPS_F + 8)

__global__ __launch_bounds__(192) void kfused(const float* __restrict__ x,
                                              float* __restrict__ out)
{
    extern __shared__ float sm[];
    float* tile = sm;                       // [d][yy][xx] = d*360 + yy*36 + xx
    float* wcls = sm + TILE_F;              // [slot][zc*225 + s]
    float* Mps  = sm + TILE_F + WCLS_F;     // [p][961]
    float* offs = Mps + MPS_F;              // [p][2]

    int tx = threadIdx.x, ty = threadIdx.y;
    int tid = ty*32 + tx;
    int gx0 = blockIdx.x*32 - 2, gy0 = blockIdx.y*6 - 2;

    if (tid < 8) offs[tid] = ((const float*)d_offp)[tid];
    // block edge classes: which y/x boundary classes this block can touch
    int oylo = blockIdx.y*6, oyhi = oylo + 5;
    int oxlo = blockIdx.x*32, oxhi = oxlo + 31;
    int yec = (oylo == 0) ? 1 : ((oyhi >= HO-1) ? 2 : 0);
    int xec = (oxlo == 0) ? 1 : ((oxhi >= WO-1) ? 2 : 0);

    // load 4 class-sets (slot: bit0 = y-edge, bit1 = x-edge)
    for (int t = tid; t < WCLS_F; t += 192) {
        int slot = t / 1125, r = t % 1125;
        int ys = (slot & 1) ? yec : 0;
        int xs = (slot & 2) ? xec : 0;
        int zc = r / 225;
        wcls[t] = d_gcls[((zc*3 + ys)*3 + xs)*225 + (r % 225)];
    }
    // load mix matrices
    for (int t = tid; t < MPS_F; t += 192) Mps[t] = d_Mp[t];
    __syncthreads();   // offs ready before tile-load bilinear uses it

    // ---- bilinear halo tile (computed from x directly) ----
    for (int t = tid; t < 360; t += 192) {
        int yy = t / 36, xx = t % 36;
        int gy = gy0 + yy, gx = gx0 + xx;
        if (gy < 0 || gy >= HO || gx < 0 || gx >= WO) {
            #pragma unroll 1
            for (int c = 0; c < CC; c++) tile[c*360 + t] = 0.f;
        } else {
            int p = ((gy & 1) << 1) | (gx & 1);
            float ix = (gx + 0.5f)*0.5f - 0.5f + offs[p*2+0];
            float iy = (gy + 0.5f)*0.5f - 0.5f + offs[p*2+1];
            float x0f = floorf(ix), y0f = floorf(iy);
            float wx1 = ix - x0f, wy1 = iy - y0f;
            int x0 = (int)x0f, y0 = (int)y0f;
            float vx0 = (x0   >= 0 && x0   <= WI-1) ? 1.f : 0.f;
            float vx1 = (x0+1 >= 0 && x0+1 <= WI-1) ? 1.f : 0.f;
            float vy0 = (y0   >= 0 && y0   <= HI-1) ? 1.f : 0.f;
            float vy1 = (y0+1 >= 0 && y0+1 <= HI-1) ? 1.f : 0.f;
            int xi0 = min(max(x0,   0), WI-1), xi1 = min(max(x0+1, 0), WI-1);
            int yi0 = min(max(y0,   0), HI-1), yi1 = min(max(y0+1, 0), HI-1);
            float w00 = (1.f-wy1)*(1.f-wx1)*vy0*vx0;
            float w01 = (1.f-wy1)*wx1*vy0*vx1;
            float w10 = wy1*(1.f-wx1)*vy1*vx0;
            float w11 = wy1*wx1*vy1*vx1;
            int b00 = yi0*WI + xi0, b01 = yi0*WI + xi1;
            int b10 = yi1*WI + xi0, b11 = yi1*WI + xi1;
            #pragma unroll 1
            for (int c = 0; c < CC; c++) {
                const float* xc = x + c*(HI*WI);
                tile[c*360 + t] = w00*__ldg(xc+b00) + w01*__ldg(xc+b01)
                                + w10*__ldg(xc+b10) + w11*__ldg(xc+b11);
            }
        }
    }
    __syncthreads();

    int oy = blockIdx.y*6 + ty, ox = blockIdx.x*32 + tx;
    if (oy >= HO) return;

    int yfl = (oy == 0 || oy == HO-1) ? 1 : 0;
    int xfl = (ox == 0 || ox == WO-1) ? 1 : 0;
    const float* gY = wcls + (yfl + 2*xfl)*1125;   // + zc*225 selects z-class

    float acc[CC];
    const float* ctr = tile + (ty+2)*36 + (tx+2);
    #pragma unroll
    for (int d = 0; d < CC; d++) acc[d] = ctr[d*360];   // residual (+fea)

    #pragma unroll 1
    for (int sy = 0; sy < 5; sy++) {
        #pragma unroll 1
        for (int sx = 0; sx < 5; sx++) {
            int t0 = sy*5 + sx;
            const float* tp = tile + (ty+sy)*36 + (tx+sx);
            float v[CC];
            #pragma unroll
            for (int d = 0; d < CC; d++) v[d] = tp[d*360];

            // interior depths d=2..28 (zc=2)
            #pragma unroll
            for (int sz = 0; sz < 9; sz++) {
                float gv = gY[2*225 + sz*25 + t0];
                #pragma unroll
                for (int d = 2; d <= 28; d++) {
                    int src = d + sz - 4;
                    if (src >= 0 && src < CC) acc[d] += gv * v[src];
                }
            }
            // d=0 (zc=0): sz 4..8, src=sz-4
            #pragma unroll
            for (int sz = 4; sz < 9; sz++)
                acc[0] += gY[0*225 + sz*25 + t0] * v[sz-4];
            // d=1 (zc=1): sz 3..8, src=sz-3
            #pragma unroll
            for (int sz = 3; sz < 9; sz++)
                acc[1] += gY[1*225 + sz*25 + t0] * v[sz-3];
            // d=29 (zc=3): sz 0..5, src=25+sz
            #pragma unroll
            for (int sz = 0; sz < 6; sz++)
                acc[29] += gY[3*225 + sz*25 + t0] * v[25+sz];
            // d=30 (zc=4): sz 0..4, src=26+sz
            #pragma unroll
            for (int sz = 0; sz < 5; sz++)
                acc[30] += gY[4*225 + sz*25 + t0] * v[26+sz];
        }
    }

    // ---- per-pixel channel mix + fea0, write out ----
    const float* M = Mps + (((oy & 1) << 1) | (ox & 1))*961;
    int pix = oy*WO + ox;
    #pragma unroll 1
    for (int ii = 0; ii < CC; ii++) {
        float a = ctr[ii*360];              // + fea0
        const float* Mr = M + ii*31;
        #pragma unroll
        for (int jj = 0; jj < CC; jj++) a += Mr[jj]*acc[jj];
        out[ii*NPIX + pix] = a;
    }
}

// ============================ launch ============================
extern "C" void kernel_launch(void* const* d_in, const int* in_sizes, int n_in,
                              void* d_out, int out_size)
{
    const float* x   = (const float*)d_in[0];
    // d_in[1] = scale (always 2; parity tables assume it)
    const float* WE  = (const float*)d_in[2];
    const float* WC  = (const float*)d_in[3];
    const float* W2  = (const float*)d_in[4];
    const float* bw1 = (const float*)d_in[5];
    const float* bb1 = (const float*)d_in[6];
    const float* bw2 = (const float*)d_in[7];
    const float* bb2 = (const float*)d_in[8];
    const float* r2w = (const float*)d_in[9];
    const float* r2b = (const float*)d_in[10];
    const float* ow  = (const float*)d_in[11];
    const float* ob  = (const float*)d_in[12];
    const float* l1w = (const float*)d_in[13];
    const float* l1b = (const float*)d_in[14];
    const float* l2w = (const float*)d_in[15];
    const float* l2b = (const float*)d_in[16];
    float* out = (float*)d_out;

    static int smem_set = 0;
    if (!smem_set) {
        cudaFuncSetAttribute(kfused, cudaFuncAttributeMaxDynamicSharedMemorySize,
                             SMEM_F * (int)sizeof(float));
        smem_set = 1;
    }

    k0a_precompute<<<1, 256>>>(WE, WC, bw1, bb1, bw2, bb2,
                               r2w, r2b, ow, ob, l1w, l1b, l2w, l2b);
    k0b_tables<<<49, 256>>>(W2);
    kfused<<<dim3(WO/32, (HO+5)/6), dim3(32, 6), SMEM_F*(int)sizeof(float)>>>(x, out);
}

// round 4
// speedup vs baseline: 15.9230x; 1.0230x over previous
#include <cuda_runtime.h>
#include <math.h>

#define CC 31
#define HO 256
#define WO 256
#define NPIX (HO*WO)          // 65536
#define HI 128
#define WI 128

// ---------------- static device scratch ----------------
__device__ float d_gcls[5*3*3*225]; // 45 boundary-class composed 9x5x5 kernels
__device__ float d_offp[4][2];      // per-parity offsets (p = (i&1)*2 | (j&1))
__device__ float d_Mp[4*961];       // per-parity 31x31 mixing matrices

// class membership: zc: 0->d=0, 1->d=1, 2->interior, 3->d=29, 4->d=30
__device__ __forceinline__ bool inQz(int zc, int qz) {
    switch (zc) {
        case 0: return qz >= 2;
        case 1: return qz >= 1;
        case 2: return true;
        case 3: return qz <= 3;
        default: return qz <= 2;
    }
}
// yc/xc: 0->interior, 1->low edge, 2->high edge
__device__ __forceinline__ bool inQ3(int c, int q) {
    return (c == 0) || (c == 1 ? q >= 1 : q <= 1);
}

// ============================ k0: all precompute, one block, smem-staged ============================
__global__ __launch_bounds__(256) void k0_all(
    const float* __restrict__ WE,  // (4,32,1,5,3,3)
    const float* __restrict__ WC,  // (4,1,32,5,3,3)
    const float* __restrict__ W2,  // (4,31,31,1,1)
    const float* __restrict__ bw1, const float* __restrict__ bb1,   // (64,3),(64)
    const float* __restrict__ bw2, const float* __restrict__ bb2,   // (64,64),(64)
    const float* __restrict__ r2w, const float* __restrict__ r2b,   // (4,64),(4)
    const float* __restrict__ ow,  const float* __restrict__ ob,    // (2,64),(2)
    const float* __restrict__ l1w, const float* __restrict__ l1b,   // (64,2),(64)
    const float* __restrict__ l2w, const float* __restrict__ l2b)   // (4,64),(4)
{
    // smem staging of all small weights + workspaces
    __shared__ float s_bw1[192], s_bb1[64], s_bw2[4096], s_bb2[64];
    __shared__ float s_r2w[256], s_r2b[4], s_ow[128], s_ob[2];
    __shared__ float s_l1w[128], s_l1b[64], s_l2w[256], s_l2b[4];
    __shared__ float e1s[4][64], e2s[4][64];
    __shared__ float rsum_s[4], r2s[4][4];
    __shared__ float h1scr[64];
    __shared__ float wem[32*45], wcm[32*45];
    __shared__ float G2s[45*45];

    int tid = threadIdx.x;   // 256 threads

    // ---- phase 0: stage everything (parallel, one DRAM round trip) ----
    for (int t = tid; t < 192;  t += 256) s_bw1[t] = bw1[t];
    for (int t = tid; t < 64;   t += 256) s_bb1[t] = bb1[t];
    for (int t = tid; t < 4096; t += 256) s_bw2[t] = bw2[t];
    for (int t = tid; t < 64;   t += 256) s_bb2[t] = bb2[t];
    for (int t = tid; t < 256;  t += 256) s_r2w[t] = r2w[t];
    for (int t = tid; t < 4;    t += 256) s_r2b[t] = r2b[t];
    for (int t = tid; t < 128;  t += 256) s_ow[t]  = ow[t];
    for (int t = tid; t < 2;    t += 256) s_ob[t]  = ob[t];
    for (int t = tid; t < 128;  t += 256) s_l1w[t] = l1w[t];
    for (int t = tid; t < 64;   t += 256) s_l1b[t] = l1b[t];
    for (int t = tid; t < 256;  t += 256) s_l2w[t] = l2w[t];
    for (int t = tid; t < 4;    t += 256) s_l2b[t] = l2b[t];
    __syncthreads();

    // ---- parity MLP layer1 (4 parities x 64 units) ----
    {
        int p = tid >> 6, o = tid & 63;
        float ch = (p & 2) ? 0.25f : -0.25f;
        float cw = (p & 1) ? 0.25f : -0.25f;
        float a = s_bw1[o*3+0]*0.5f + s_bw1[o*3+1]*ch + s_bw1[o*3+2]*cw + s_bb1[o];
        e1s[p][o] = a > 0.f ? a : 0.f;
    }
    __syncthreads();
    {
        int p = tid >> 6, o = tid & 63;
        float a = s_bb2[o];
        #pragma unroll 8
        for (int i = 0; i < 64; i++) a += s_bw2[o*64+i]*e1s[p][i];
        e2s[p][o] = a > 0.f ? a : 0.f;
    }
    __syncthreads();

    // ---- heads (tid<24) + routing rsum (tid==64, from smem, cheap) ----
    if (tid < 24) {
        int p = tid / 6, u = tid % 6;
        if (u < 2) {
            float a = s_ob[u];
            for (int i = 0; i < 64; i++) a += s_ow[u*64+i]*e2s[p][i];
            d_offp[p][u] = a;
        } else {
            int e = u - 2;
            float a = s_r2b[e];
            for (int i = 0; i < 64; i++) a += s_r2w[e*64+i]*e2s[p][i];
            r2s[p][e] = 1.f/(1.f+expf(-a));
        }
    }
    if (tid == 64) {
        float rs[4] = {0.f,0.f,0.f,0.f};
        for (int r = 0; r < 2; r++) {
            float chr = r ? 0.25f : -0.25f;
            for (int o = 0; o < 64; o++) {
                float a = s_l1w[o*2+0]*0.5f + s_l1w[o*2+1]*chr + s_l1b[o];
                h1scr[o] = a > 0.f ? a : 0.f;
            }
            float lg[4]; float m = -1e30f;
            for (int e = 0; e < 4; e++) {
                float a = s_l2b[e];
                for (int o = 0; o < 64; o++) a += s_l2w[e*64+o]*h1scr[o];
                lg[e] = a; if (a > m) m = a;
            }
            float s = 0.f;
            for (int e = 0; e < 4; e++) { lg[e] = expf(lg[e]-m); s += lg[e]; }
            for (int e = 0; e < 4; e++) rs[e] += lg[e]/s;
        }
        for (int e = 0; e < 4; e++) rsum_s[e] = rs[e];
    }
    __syncthreads();

    // ---- rsum-mixed conv weights (coalesced global reads of WE/WC) ----
    {
        float r0 = rsum_s[0], r1 = rsum_s[1], r2 = rsum_s[2], r3 = rsum_s[3];
        for (int idx = tid; idx < 32*45; idx += 256) {
            wem[idx] = r0*WE[idx] + r1*WE[1440+idx] + r2*WE[2880+idx] + r3*WE[4320+idx];
            wcm[idx] = r0*WC[idx] + r1*WC[1440+idx] + r2*WC[2880+idx] + r3*WC[4320+idx];
        }
    }
    __syncthreads();

    // ---- G2[q][r] = sum_k wc_k[q] * we_k[r] ----
    for (int idx = tid; idx < 45*45; idx += 256) {
        int q = idx / 45, r = idx % 45;
        float acc = 0.f;
        #pragma unroll 8
        for (int k = 0; k < 32; k++)
            acc += wcm[k*45+q]*wem[k*45+r];
        G2s[idx] = acc;
    }
    __syncthreads();

    // ---- 45 boundary-class composed kernels ----
    for (int e = tid; e < 45*225; e += 256) {
        int cls = e / 225, s = e % 225;
        int zc = cls / 9, yc = (cls % 9) / 3, xc = cls % 3;
        int sz = s / 25, sy = (s % 25) / 5, sx = s % 5;
        float acc = 0.f;
        for (int qz = 0; qz < 5; qz++) {
            if (!inQz(zc, qz)) continue;
            int rz = sz - qz; if (rz < 0 || rz > 4) continue;
            for (int qy = 0; qy < 3; qy++) {
                if (!inQ3(yc, qy)) continue;
                int ry = sy - qy; if (ry < 0 || ry > 2) continue;
                for (int qx = 0; qx < 3; qx++) {
                    if (!inQ3(xc, qx)) continue;
                    int rx = sx - qx; if (rx < 0 || rx > 2) continue;
                    acc += G2s[(qz*9+qy*3+qx)*45 + rz*9+ry*3+rx];
                }
            }
        }
        d_gcls[e] = acc;
    }

    // ---- per-parity mixing matrices ----
    for (int idx = tid; idx < 4*961; idx += 256) {
        int p = idx / 961, ij = idx % 961;
        d_Mp[idx] = r2s[p][0]*W2[ij] + r2s[p][1]*W2[961+ij]
                  + r2s[p][2]*W2[2*961+ij] + r2s[p][3]*W2[3*961+ij];
    }
}

// ============================ fused: bilinear + exact conv + residual + mix ============================
// block (32,8): 32x8 output pixels, all 31 depths. grid 8x32 = 256 blocks -> single wave @2/SM.
// dynamic smem: tile[31][12][36] | wcls[4][5*225] | Mps[4*961] | offs[8]
#define TROWS 12
#define TILE_F (CC*TROWS*36)
#define WCLS_F (4*5*225)
#define MPS_F  (4*961)
#define SMEM_F (TILE_F + WCLS_F + MPS_F + 8)

__global__ __launch_bounds__(256, 2) void kfused(const float* __restrict__ x,
                                                 float* __restrict__ out)
{
    extern __shared__ float sm[];
    float* tile = sm;                       // [d][yy][xx] = d*432 + yy*36 + xx
    float* wcls = sm + TILE_F;              // [slot][zc*225 + s]
    float* Mps  = sm + TILE_F + WCLS_F;     // [p][961]
    float* offs = Mps + MPS_F;              // [p][2]

    int tx = threadIdx.x, ty = threadIdx.y;
    int tid = ty*32 + tx;
    int gx0 = blockIdx.x*32 - 2, gy0 = blockIdx.y*8 - 2;

    if (tid < 8) offs[tid] = ((const float*)d_offp)[tid];
    // block edge classes
    int oylo = blockIdx.y*8, oyhi = oylo + 7;
    int oxlo = blockIdx.x*32, oxhi = oxlo + 31;
    int yec = (oylo == 0) ? 1 : ((oyhi >= HO-1) ? 2 : 0);
    int xec = (oxlo == 0) ? 1 : ((oxhi >= WO-1) ? 2 : 0);

    // load 4 class-sets (slot: bit0 = y-edge, bit1 = x-edge)
    for (int t = tid; t < WCLS_F; t += 256) {
        int slot = t / 1125, r = t % 1125;
        int ys = (slot & 1) ? yec : 0;
        int xs = (slot & 2) ? xec : 0;
        int zc = r / 225;
        wcls[t] = d_gcls[((zc*3 + ys)*3 + xs)*225 + (r % 225)];
    }
    for (int t = tid; t < MPS_F; t += 256) Mps[t] = d_Mp[t];
    __syncthreads();   // offs ready before bilinear uses it

    // ---- bilinear halo tile from x ----
    for (int t = tid; t < TROWS*36; t += 256) {
        int yy = t / 36, xx = t % 36;
        int gy = gy0 + yy, gx = gx0 + xx;
        if (gy < 0 || gy >= HO || gx < 0 || gx >= WO) {
            #pragma unroll 1
            for (int c = 0; c < CC; c++) tile[c*(TROWS*36) + t] = 0.f;
        } else {
            int p = ((gy & 1) << 1) | (gx & 1);
            float ix = (gx + 0.5f)*0.5f - 0.5f + offs[p*2+0];
            float iy = (gy + 0.5f)*0.5f - 0.5f + offs[p*2+1];
            float x0f = floorf(ix), y0f = floorf(iy);
            float wx1 = ix - x0f, wy1 = iy - y0f;
            int x0 = (int)x0f, y0 = (int)y0f;
            float vx0 = (x0   >= 0 && x0   <= WI-1) ? 1.f : 0.f;
            float vx1 = (x0+1 >= 0 && x0+1 <= WI-1) ? 1.f : 0.f;
            float vy0 = (y0   >= 0 && y0   <= HI-1) ? 1.f : 0.f;
            float vy1 = (y0+1 >= 0 && y0+1 <= HI-1) ? 1.f : 0.f;
            int xi0 = min(max(x0,   0), WI-1), xi1 = min(max(x0+1, 0), WI-1);
            int yi0 = min(max(y0,   0), HI-1), yi1 = min(max(y0+1, 0), HI-1);
            float w00 = (1.f-wy1)*(1.f-wx1)*vy0*vx0;
            float w01 = (1.f-wy1)*wx1*vy0*vx1;
            float w10 = wy1*(1.f-wx1)*vy1*vx0;
            float w11 = wy1*wx1*vy1*vx1;
            int b00 = yi0*WI + xi0, b01 = yi0*WI + xi1;
            int b10 = yi1*WI + xi0, b11 = yi1*WI + xi1;
            #pragma unroll 1
            for (int c = 0; c < CC; c++) {
                const float* xc = x + c*(HI*WI);
                tile[c*(TROWS*36) + t] = w00*__ldg(xc+b00) + w01*__ldg(xc+b01)
                                       + w10*__ldg(xc+b10) + w11*__ldg(xc+b11);
            }
        }
    }
    __syncthreads();

    int oy = blockIdx.y*8 + ty, ox = blockIdx.x*32 + tx;

    int yfl = (oy == 0 || oy == HO-1) ? 1 : 0;
    int xfl = (ox == 0 || ox == WO-1) ? 1 : 0;
    const float* gY = wcls + (yfl + 2*xfl)*1125;   // + zc*225 selects z-class

    float acc[CC];
    const float* ctr = tile + (ty+2)*36 + (tx+2);
    #pragma unroll
    for (int d = 0; d < CC; d++) acc[d] = ctr[d*(TROWS*36)];   // residual (+fea)

    #pragma unroll 1
    for (int sy = 0; sy < 5; sy++) {
        #pragma unroll 1
        for (int sx = 0; sx < 5; sx++) {
            int t0 = sy*5 + sx;
            const float* tp = tile + (ty+sy)*36 + (tx+sx);
            float v[CC];
            #pragma unroll
            for (int d = 0; d < CC; d++) v[d] = tp[d*(TROWS*36)];

            // interior depths d=2..28 (zc=2)
            #pragma unroll
            for (int sz = 0; sz < 9; sz++) {
                float gv = gY[2*225 + sz*25 + t0];
                #pragma unroll
                for (int d = 2; d <= 28; d++) {
                    int src = d + sz - 4;
                    if (src >= 0 && src < CC) acc[d] += gv * v[src];
                }
            }
            // d=0 (zc=0): sz 4..8, src=sz-4
            #pragma unroll
            for (int sz = 4; sz < 9; sz++)
                acc[0] += gY[0*225 + sz*25 + t0] * v[sz-4];
            // d=1 (zc=1): sz 3..8, src=sz-3
            #pragma unroll
            for (int sz = 3; sz < 9; sz++)
                acc[1] += gY[1*225 + sz*25 + t0] * v[sz-3];
            // d=29 (zc=3): sz 0..5, src=25+sz
            #pragma unroll
            for (int sz = 0; sz < 6; sz++)
                acc[29] += gY[3*225 + sz*25 + t0] * v[25+sz];
            // d=30 (zc=4): sz 0..4, src=26+sz
            #pragma unroll
            for (int sz = 0; sz < 5; sz++)
                acc[30] += gY[4*225 + sz*25 + t0] * v[26+sz];
        }
    }

    // ---- per-pixel channel mix + fea0, write out ----
    const float* M = Mps + (((oy & 1) << 1) | (ox & 1))*961;
    int pix = oy*WO + ox;
    #pragma unroll 1
    for (int ii = 0; ii < CC; ii++) {
        float a = ctr[ii*(TROWS*36)];       // + fea0
        const float* Mr = M + ii*31;
        #pragma unroll
        for (int jj = 0; jj < CC; jj++) a += Mr[jj]*acc[jj];
        out[ii*NPIX + pix] = a;
    }
}

// ============================ launch ============================
extern "C" void kernel_launch(void* const* d_in, const int* in_sizes, int n_in,
                              void* d_out, int out_size)
{
    const float* x   = (const float*)d_in[0];
    // d_in[1] = scale (always 2; parity tables assume it)
    const float* WE  = (const float*)d_in[2];
    const float* WC  = (const float*)d_in[3];
    const float* W2  = (const float*)d_in[4];
    const float* bw1 = (const float*)d_in[5];
    const float* bb1 = (const float*)d_in[6];
    const float* bw2 = (const float*)d_in[7];
    const float* bb2 = (const float*)d_in[8];
    const float* r2w = (const float*)d_in[9];
    const float* r2b = (const float*)d_in[10];
    const float* ow  = (const float*)d_in[11];
    const float* ob  = (const float*)d_in[12];
    const float* l1w = (const float*)d_in[13];
    const float* l1b = (const float*)d_in[14];
    const float* l2w = (const float*)d_in[15];
    const float* l2b = (const float*)d_in[16];
    float* out = (float*)d_out;

    static int smem_set = 0;
    if (!smem_set) {
        cudaFuncSetAttribute(kfused, cudaFuncAttributeMaxDynamicSharedMemorySize,
                             SMEM_F * (int)sizeof(float));
        smem_set = 1;
    }

    k0_all<<<1, 256>>>(WE, WC, W2, bw1, bb1, bw2, bb2,
                       r2w, r2b, ow, ob, l1w, l1b, l2w, l2b);
    kfused<<<dim3(WO/32, HO/8), dim3(32, 8), SMEM_F*(int)sizeof(float)>>>(x, out);
}

// round 5
// speedup vs baseline: 22.5165x; 1.4141x over previous
#include <cuda_runtime.h>
#include <math.h>

#define CC 31
#define HO 256
#define WO 256
#define NPIX (HO*WO)          // 65536
#define HI 128
#define WI 128

// ---------------- static device scratch ----------------
__device__ float d_G2[45*45];       // composed tap-pair matrix
__device__ float d_gcls[5*3*3*225]; // 45 boundary-class composed 9x5x5 kernels
__device__ float d_offp[4][2];      // per-parity offsets (p = (i&1)*2 | (j&1))
__device__ float d_r2p[4][4];       // per-parity routing2 (sigmoid)
__device__ float d_Mp[4*961];       // per-parity 31x31 mixing matrices

// class membership: zc: 0->d=0, 1->d=1, 2->interior, 3->d=29, 4->d=30
__device__ __forceinline__ bool inQz(int zc, int qz) {
    switch (zc) {
        case 0: return qz >= 2;
        case 1: return qz >= 1;
        case 2: return true;
        case 3: return qz <= 3;
        default: return qz <= 2;
    }
}
// yc/xc: 0->interior, 1->low edge, 2->high edge
__device__ __forceinline__ bool inQ3(int c, int q) {
    return (c == 0) || (c == 1 ? q >= 1 : q <= 1);
}

// ============================ k0a: lean scalar precompute (1 block) ============================
__global__ __launch_bounds__(256) void k0a(
    const float* __restrict__ WE,  // (4,32,1,5,3,3)
    const float* __restrict__ WC,  // (4,1,32,5,3,3)
    const float* __restrict__ bw1, const float* __restrict__ bb1,
    const float* __restrict__ bw2, const float* __restrict__ bb2,
    const float* __restrict__ r2w, const float* __restrict__ r2b,
    const float* __restrict__ ow,  const float* __restrict__ ob,
    const float* __restrict__ l1w, const float* __restrict__ l1b,
    const float* __restrict__ l2w, const float* __restrict__ l2b)
{
    __shared__ float s_bw1[192], s_bb1[64], s_bw2[4096], s_bb2[64];
    __shared__ float s_r2w[256], s_r2b[4], s_ow[128], s_ob[2];
    __shared__ float s_l1w[128], s_l1b[64], s_l2w[256], s_l2b[4];
    __shared__ float e1s[4][64], e2s[4][64];
    __shared__ float rsum_s[4];
    __shared__ float h1scr[64];
    __shared__ float wem[32*45], wcm[32*45];

    int tid = threadIdx.x;

    // stage all small weights (parallel)
    for (int t = tid; t < 192;  t += 256) s_bw1[t] = bw1[t];
    for (int t = tid; t < 64;   t += 256) s_bb1[t] = bb1[t];
    for (int t = tid; t < 4096; t += 256) s_bw2[t] = bw2[t];
    for (int t = tid; t < 64;   t += 256) s_bb2[t] = bb2[t];
    for (int t = tid; t < 256;  t += 256) s_r2w[t] = r2w[t];
    for (int t = tid; t < 4;    t += 256) s_r2b[t] = r2b[t];
    for (int t = tid; t < 128;  t += 256) s_ow[t]  = ow[t];
    for (int t = tid; t < 2;    t += 256) s_ob[t]  = ob[t];
    for (int t = tid; t < 128;  t += 256) s_l1w[t] = l1w[t];
    for (int t = tid; t < 64;   t += 256) s_l1b[t] = l1b[t];
    for (int t = tid; t < 256;  t += 256) s_l2w[t] = l2w[t];
    for (int t = tid; t < 4;    t += 256) s_l2b[t] = l2b[t];
    __syncthreads();

    // parity MLP
    {
        int p = tid >> 6, o = tid & 63;
        float ch = (p & 2) ? 0.25f : -0.25f;
        float cw = (p & 1) ? 0.25f : -0.25f;
        float a = s_bw1[o*3+0]*0.5f + s_bw1[o*3+1]*ch + s_bw1[o*3+2]*cw + s_bb1[o];
        e1s[p][o] = a > 0.f ? a : 0.f;
    }
    __syncthreads();
    {
        int p = tid >> 6, o = tid & 63;
        float a = s_bb2[o];
        #pragma unroll 8
        for (int i = 0; i < 64; i++) a += s_bw2[o*64+i]*e1s[p][i];
        e2s[p][o] = a > 0.f ? a : 0.f;
    }
    __syncthreads();

    // heads + routing rsum
    if (tid < 24) {
        int p = tid / 6, u = tid % 6;
        if (u < 2) {
            float a = s_ob[u];
            for (int i = 0; i < 64; i++) a += s_ow[u*64+i]*e2s[p][i];
            d_offp[p][u] = a;
        } else {
            int e = u - 2;
            float a = s_r2b[e];
            for (int i = 0; i < 64; i++) a += s_r2w[e*64+i]*e2s[p][i];
            d_r2p[p][e] = 1.f/(1.f+expf(-a));
        }
    }
    if (tid == 64) {
        float rs[4] = {0.f,0.f,0.f,0.f};
        for (int r = 0; r < 2; r++) {
            float chr = r ? 0.25f : -0.25f;
            for (int o = 0; o < 64; o++) {
                float a = s_l1w[o*2+0]*0.5f + s_l1w[o*2+1]*chr + s_l1b[o];
                h1scr[o] = a > 0.f ? a : 0.f;
            }
            float lg[4]; float m = -1e30f;
            for (int e = 0; e < 4; e++) {
                float a = s_l2b[e];
                for (int o = 0; o < 64; o++) a += s_l2w[e*64+o]*h1scr[o];
                lg[e] = a; if (a > m) m = a;
            }
            float s = 0.f;
            for (int e = 0; e < 4; e++) { lg[e] = expf(lg[e]-m); s += lg[e]; }
            for (int e = 0; e < 4; e++) rs[e] += lg[e]/s;
        }
        for (int e = 0; e < 4; e++) rsum_s[e] = rs[e];
    }
    __syncthreads();

    // rsum-mixed conv weights
    {
        float r0 = rsum_s[0], r1 = rsum_s[1], r2 = rsum_s[2], r3 = rsum_s[3];
        for (int idx = tid; idx < 32*45; idx += 256) {
            wem[idx] = r0*WE[idx] + r1*WE[1440+idx] + r2*WE[2880+idx] + r3*WE[4320+idx];
            wcm[idx] = r0*WC[idx] + r1*WC[1440+idx] + r2*WC[2880+idx] + r3*WC[4320+idx];
        }
    }
    __syncthreads();

    // G2[q][r] = sum_k wc_k[q] * we_k[r]
    for (int idx = tid; idx < 45*45; idx += 256) {
        int q = idx / 45, r = idx % 45;
        float a0 = 0.f, a1 = 0.f;
        #pragma unroll
        for (int k = 0; k < 32; k += 2) {
            a0 += wcm[k*45+q]*wem[k*45+r];
            a1 += wcm[(k+1)*45+q]*wem[(k+1)*45+r];
        }
        d_G2[idx] = a0 + a1;
    }
}

// ============================ k0b: class kernels + mix matrices (49 blocks) ============================
__global__ __launch_bounds__(256) void k0b(const float* __restrict__ W2)
{
    int tid = threadIdx.x;
    int bid = blockIdx.x;
    if (bid < 45) {
        __shared__ float G2s[45*45];
        for (int t = tid; t < 45*45; t += 256) G2s[t] = d_G2[t];
        __syncthreads();
        if (tid >= 225) return;
        int cls = bid;
        int zc = cls / 9, yc = (cls % 9) / 3, xc = cls % 3;
        int s = tid;
        int sz = s / 25, sy = (s % 25) / 5, sx = s % 5;
        float acc = 0.f;
        for (int qz = 0; qz < 5; qz++) {
            if (!inQz(zc, qz)) continue;
            int rz = sz - qz; if (rz < 0 || rz > 4) continue;
            for (int qy = 0; qy < 3; qy++) {
                if (!inQ3(yc, qy)) continue;
                int ry = sy - qy; if (ry < 0 || ry > 2) continue;
                for (int qx = 0; qx < 3; qx++) {
                    if (!inQ3(xc, qx)) continue;
                    int rx = sx - qx; if (rx < 0 || rx > 2) continue;
                    acc += G2s[(qz*9+qy*3+qx)*45 + rz*9+ry*3+rx];
                }
            }
        }
        d_gcls[cls*225 + s] = acc;
    } else {
        int p = bid - 45;
        float r0 = d_r2p[p][0], r1 = d_r2p[p][1], r2 = d_r2p[p][2], r3 = d_r2p[p][3];
        for (int ij = tid; ij < 961; ij += 256)
            d_Mp[p*961 + ij] = r0*W2[ij] + r1*W2[961+ij] + r2*W2[2*961+ij] + r3*W2[3*961+ij];
    }
}

// ============================ fused: bilinear + exact conv + residual + mix ============================
#define TROWS 12
#define TS (TROWS*36)
#define TILE_F (CC*TS)
#define WCLS_F (4*5*225)
#define MPS_F  (4*961)
#define SMEM_F (TILE_F + WCLS_F + MPS_F + 8)

__global__ __launch_bounds__(256, 2) void kfused(const float* __restrict__ x,
                                                 float* __restrict__ out)
{
    extern __shared__ float sm[];
    float* tile = sm;                       // [d][yy][xx] = d*432 + yy*36 + xx
    float* wcls = sm + TILE_F;              // [slot][zc*225 + s]
    float* Mps  = sm + TILE_F + WCLS_F;     // [p][961]
    float* offs = Mps + MPS_F;              // [p][2]

    int tx = threadIdx.x, ty = threadIdx.y;
    int tid = ty*32 + tx;
    int gx0 = blockIdx.x*32 - 2, gy0 = blockIdx.y*8 - 2;

    if (tid < 8) offs[tid] = ((const float*)d_offp)[tid];
    int oylo = blockIdx.y*8, oyhi = oylo + 7;
    int oxlo = blockIdx.x*32, oxhi = oxlo + 31;
    int yec = (oylo == 0) ? 1 : ((oyhi >= HO-1) ? 2 : 0);
    int xec = (oxlo == 0) ? 1 : ((oxhi >= WO-1) ? 2 : 0);

    for (int t = tid; t < WCLS_F; t += 256) {
        int slot = t / 1125, r = t % 1125;
        int ys = (slot & 1) ? yec : 0;
        int xs = (slot & 2) ? xec : 0;
        int zc = r / 225;
        wcls[t] = d_gcls[((zc*3 + ys)*3 + xs)*225 + (r % 225)];
    }
    for (int t = tid; t < MPS_F; t += 256) Mps[t] = d_Mp[t];
    __syncthreads();   // offs ready before bilinear uses it

    // ---- bilinear halo tile from x (channels unrolled x4 for load MLP) ----
    for (int t = tid; t < TROWS*36; t += 256) {
        int yy = t / 36, xx = t % 36;
        int gy = gy0 + yy, gx = gx0 + xx;
        if (gy < 0 || gy >= HO || gx < 0 || gx >= WO) {
            #pragma unroll 4
            for (int c = 0; c < CC; c++) tile[c*TS + t] = 0.f;
        } else {
            int p = ((gy & 1) << 1) | (gx & 1);
            float ix = (gx + 0.5f)*0.5f - 0.5f + offs[p*2+0];
            float iy = (gy + 0.5f)*0.5f - 0.5f + offs[p*2+1];
            float x0f = floorf(ix), y0f = floorf(iy);
            float wx1 = ix - x0f, wy1 = iy - y0f;
            int x0 = (int)x0f, y0 = (int)y0f;
            float vx0 = (x0   >= 0 && x0   <= WI-1) ? 1.f : 0.f;
            float vx1 = (x0+1 >= 0 && x0+1 <= WI-1) ? 1.f : 0.f;
            float vy0 = (y0   >= 0 && y0   <= HI-1) ? 1.f : 0.f;
            float vy1 = (y0+1 >= 0 && y0+1 <= HI-1) ? 1.f : 0.f;
            int xi0 = min(max(x0,   0), WI-1), xi1 = min(max(x0+1, 0), WI-1);
            int yi0 = min(max(y0,   0), HI-1), yi1 = min(max(y0+1, 0), HI-1);
            float w00 = (1.f-wy1)*(1.f-wx1)*vy0*vx0;
            float w01 = (1.f-wy1)*wx1*vy0*vx1;
            float w10 = wy1*(1.f-wx1)*vy1*vx0;
            float w11 = wy1*wx1*vy1*vx1;
            int b00 = yi0*WI + xi0, b01 = yi0*WI + xi1;
            int b10 = yi1*WI + xi0, b11 = yi1*WI + xi1;
            #pragma unroll 4
            for (int c = 0; c < CC; c++) {
                const float* xc = x + c*(HI*WI);
                tile[c*TS + t] = w00*__ldg(xc+b00) + w01*__ldg(xc+b01)
                               + w10*__ldg(xc+b10) + w11*__ldg(xc+b11);
            }
        }
    }
    __syncthreads();

    int oy = blockIdx.y*8 + ty, ox = blockIdx.x*32 + tx;

    int yfl = (oy == 0 || oy == HO-1) ? 1 : 0;
    int xfl = (ox == 0 || ox == WO-1) ? 1 : 0;
    const float* gY = wcls + (yfl + 2*xfl)*1125;

    float acc[CC];
    const float* ctr = tile + (ty+2)*36 + (tx+2);
    #pragma unroll
    for (int d = 0; d < CC; d++) acc[d] = ctr[d*TS];   // residual (+fea)

    #pragma unroll 1
    for (int sy = 0; sy < 5; sy++) {
        #pragma unroll 1
        for (int sx = 0; sx < 5; sx++) {
            int t0 = sy*5 + sx;
            const float* tp = tile + (ty+sy)*36 + (tx+sx);
            float v[CC];
            #pragma unroll
            for (int d = 0; d < CC; d++) v[d] = tp[d*TS];

            // interior depths d=2..28 (zc=2)
            #pragma unroll
            for (int sz = 0; sz < 9; sz++) {
                float gv = gY[2*225 + sz*25 + t0];
                #pragma unroll
                for (int d = 2; d <= 28; d++) {
                    int src = d + sz - 4;
                    if (src >= 0 && src < CC) acc[d] += gv * v[src];
                }
            }
            #pragma unroll
            for (int sz = 4; sz < 9; sz++)
                acc[0] += gY[0*225 + sz*25 + t0] * v[sz-4];
            #pragma unroll
            for (int sz = 3; sz < 9; sz++)
                acc[1] += gY[1*225 + sz*25 + t0] * v[sz-3];
            #pragma unroll
            for (int sz = 0; sz < 6; sz++)
                acc[29] += gY[3*225 + sz*25 + t0] * v[25+sz];
            #pragma unroll
            for (int sz = 0; sz < 5; sz++)
                acc[30] += gY[4*225 + sz*25 + t0] * v[26+sz];
        }
    }

    // ---- per-pixel channel mix + fea0 (2 rows x 2 partial sums = 4 chains) ----
    const float* M = Mps + (((oy & 1) << 1) | (ox & 1))*961;
    int pix = oy*WO + ox;
    #pragma unroll 1
    for (int ii = 0; ii < 30; ii += 2) {
        const float* M0 = M + ii*31;
        const float* M1 = M0 + 31;
        float s00 = 0.f, s01 = 0.f, s10 = 0.f, s11 = 0.f;
        #pragma unroll
        for (int jj = 0; jj < 15; jj++) {
            s00 += M0[jj]*acc[jj];
            s10 += M1[jj]*acc[jj];
        }
        #pragma unroll
        for (int jj = 15; jj < 31; jj++) {
            s01 += M0[jj]*acc[jj];
            s11 += M1[jj]*acc[jj];
        }
        out[ii*NPIX + pix]     = ctr[ii*TS]     + (s00 + s01);
        out[(ii+1)*NPIX + pix] = ctr[(ii+1)*TS] + (s10 + s11);
    }
    {   // ii = 30 tail
        const float* M0 = M + 30*31;
        float s0 = 0.f, s1 = 0.f;
        #pragma unroll
        for (int jj = 0; jj < 15; jj++) s0 += M0[jj]*acc[jj];
        #pragma unroll
        for (int jj = 15; jj < 31; jj++) s1 += M0[jj]*acc[jj];
        out[30*NPIX + pix] = ctr[30*TS] + (s0 + s1);
    }
}

// ============================ launch ============================
extern "C" void kernel_launch(void* const* d_in, const int* in_sizes, int n_in,
                              void* d_out, int out_size)
{
    const float* x   = (const float*)d_in[0];
    // d_in[1] = scale (always 2; parity tables assume it)
    const float* WE  = (const float*)d_in[2];
    const float* WC  = (const float*)d_in[3];
    const float* W2  = (const float*)d_in[4];
    const float* bw1 = (const float*)d_in[5];
    const float* bb1 = (const float*)d_in[6];
    const float* bw2 = (const float*)d_in[7];
    const float* bb2 = (const float*)d_in[8];
    const float* r2w = (const float*)d_in[9];
    const float* r2b = (const float*)d_in[10];
    const float* ow  = (const float*)d_in[11];
    const float* ob  = (const float*)d_in[12];
    const float* l1w = (const float*)d_in[13];
    const float* l1b = (const float*)d_in[14];
    const float* l2w = (const float*)d_in[15];
    const float* l2b = (const float*)d_in[16];
    float* out = (float*)d_out;

    static int smem_set = 0;
    if (!smem_set) {
        cudaFuncSetAttribute(kfused, cudaFuncAttributeMaxDynamicSharedMemorySize,
                             SMEM_F * (int)sizeof(float));
        smem_set = 1;
    }

    k0a<<<1, 256>>>(WE, WC, bw1, bb1, bw2, bb2,
                    r2w, r2b, ow, ob, l1w, l1b, l2w, l2b);
    k0b<<<49, 256>>>(W2);
    kfused<<<dim3(WO/32, HO/8), dim3(32, 8), SMEM_F*(int)sizeof(float)>>>(x, out);
}

// round 6
// speedup vs baseline: 23.4537x; 1.0416x over previous
#include <cuda_runtime.h>
#include <math.h>

#define CC 31
#define HO 256
#define WO 256
#define NPIX (HO*WO)          // 65536
#define HI 128
#define WI 128

// ---------------- static device scratch ----------------
__device__ float d_G2[45*45];       // composed tap-pair matrix
__device__ float d_gcls[5*3*3*225]; // 45 boundary-class composed 9x5x5 kernels
__device__ float d_offp[4][2];      // per-parity offsets (p = (i&1)*2 | (j&1))
__device__ float d_r2p[4][4];       // per-parity routing2 (sigmoid)
__device__ float d_Mp[4*961];       // per-parity 31x31 mixing matrices

// class membership: zc: 0->d=0, 1->d=1, 2->interior, 3->d=29, 4->d=30
__device__ __forceinline__ bool inQz(int zc, int qz) {
    switch (zc) {
        case 0: return qz >= 2;
        case 1: return qz >= 1;
        case 2: return true;
        case 3: return qz <= 3;
        default: return qz <= 2;
    }
}
// yc/xc: 0->interior, 1->low edge, 2->high edge
__device__ __forceinline__ bool inQ3(int c, int q) {
    return (c == 0) || (c == 1 ? q >= 1 : q <= 1);
}

// ============================ k0a: precompute, grid=148 (beat low-grid throttle) ============================
// All blocks redundantly compute the tiny MLP pieces (identical results, benign
// duplicate writes). G2 (the only sizable piece) is distributed across blocks.
__global__ __launch_bounds__(256) void k0a(
    const float* __restrict__ WE,  // (4,32,1,5,3,3)
    const float* __restrict__ WC,  // (4,1,32,5,3,3)
    const float* __restrict__ bw1, const float* __restrict__ bb1,
    const float* __restrict__ bw2, const float* __restrict__ bb2,
    const float* __restrict__ r2w, const float* __restrict__ r2b,
    const float* __restrict__ ow,  const float* __restrict__ ob,
    const float* __restrict__ l1w, const float* __restrict__ l1b,
    const float* __restrict__ l2w, const float* __restrict__ l2b)
{
    __shared__ float s_bw1[192], s_bb1[64], s_bw2[4096], s_bb2[64];
    __shared__ float s_r2w[256], s_r2b[4], s_ow[128], s_ob[2];
    __shared__ float s_l1w[128], s_l1b[64], s_l2w[256], s_l2b[4];
    __shared__ float e1s[4][64], e2s[4][64];
    __shared__ float rsum_s[4];
    __shared__ float h1scr[64];
    __shared__ float wem[32*45], wcm[32*45];

    int tid = threadIdx.x;

    // stage all small weights (parallel; L2-shared across blocks)
    for (int t = tid; t < 192;  t += 256) s_bw1[t] = bw1[t];
    for (int t = tid; t < 64;   t += 256) s_bb1[t] = bb1[t];
    for (int t = tid; t < 4096; t += 256) s_bw2[t] = bw2[t];
    for (int t = tid; t < 64;   t += 256) s_bb2[t] = bb2[t];
    for (int t = tid; t < 256;  t += 256) s_r2w[t] = r2w[t];
    for (int t = tid; t < 4;    t += 256) s_r2b[t] = r2b[t];
    for (int t = tid; t < 128;  t += 256) s_ow[t]  = ow[t];
    for (int t = tid; t < 2;    t += 256) s_ob[t]  = ob[t];
    for (int t = tid; t < 128;  t += 256) s_l1w[t] = l1w[t];
    for (int t = tid; t < 64;   t += 256) s_l1b[t] = l1b[t];
    for (int t = tid; t < 256;  t += 256) s_l2w[t] = l2w[t];
    for (int t = tid; t < 4;    t += 256) s_l2b[t] = l2b[t];
    __syncthreads();

    // parity MLP
    {
        int p = tid >> 6, o = tid & 63;
        float ch = (p & 2) ? 0.25f : -0.25f;
        float cw = (p & 1) ? 0.25f : -0.25f;
        float a = s_bw1[o*3+0]*0.5f + s_bw1[o*3+1]*ch + s_bw1[o*3+2]*cw + s_bb1[o];
        e1s[p][o] = a > 0.f ? a : 0.f;
    }
    __syncthreads();
    {
        int p = tid >> 6, o = tid & 63;
        float a = s_bb2[o];
        #pragma unroll 8
        for (int i = 0; i < 64; i++) a += s_bw2[o*64+i]*e1s[p][i];
        e2s[p][o] = a > 0.f ? a : 0.f;
    }
    __syncthreads();

    // heads (redundant across blocks; identical values)
    if (tid < 24) {
        int p = tid / 6, u = tid % 6;
        if (u < 2) {
            float a = s_ob[u];
            for (int i = 0; i < 64; i++) a += s_ow[u*64+i]*e2s[p][i];
            d_offp[p][u] = a;
        } else {
            int e = u - 2;
            float a = s_r2b[e];
            for (int i = 0; i < 64; i++) a += s_r2w[e*64+i]*e2s[p][i];
            d_r2p[p][e] = 1.f/(1.f+expf(-a));
        }
    }
    if (tid == 64) {
        float rs[4] = {0.f,0.f,0.f,0.f};
        for (int r = 0; r < 2; r++) {
            float chr = r ? 0.25f : -0.25f;
            for (int o = 0; o < 64; o++) {
                float a = s_l1w[o*2+0]*0.5f + s_l1w[o*2+1]*chr + s_l1b[o];
                h1scr[o] = a > 0.f ? a : 0.f;
            }
            float lg[4]; float m = -1e30f;
            for (int e = 0; e < 4; e++) {
                float a = s_l2b[e];
                for (int o = 0; o < 64; o++) a += s_l2w[e*64+o]*h1scr[o];
                lg[e] = a; if (a > m) m = a;
            }
            float s = 0.f;
            for (int e = 0; e < 4; e++) { lg[e] = expf(lg[e]-m); s += lg[e]; }
            for (int e = 0; e < 4; e++) rs[e] += lg[e]/s;
        }
        for (int e = 0; e < 4; e++) rsum_s[e] = rs[e];
    }
    __syncthreads();

    // rsum-mixed conv weights (redundant; identical values)
    {
        float r0 = rsum_s[0], r1 = rsum_s[1], r2 = rsum_s[2], r3 = rsum_s[3];
        for (int idx = tid; idx < 32*45; idx += 256) {
            wem[idx] = r0*WE[idx] + r1*WE[1440+idx] + r2*WE[2880+idx] + r3*WE[4320+idx];
            wcm[idx] = r0*WC[idx] + r1*WC[1440+idx] + r2*WC[2880+idx] + r3*WC[4320+idx];
        }
    }
    __syncthreads();

    // G2[q][r] = sum_k wc_k[q] * we_k[r]  — distributed: one entry per global thread
    {
        int g = blockIdx.x*256 + tid;
        if (g < 45*45) {
            int q = g / 45, r = g % 45;
            float a0 = 0.f, a1 = 0.f;
            #pragma unroll
            for (int k = 0; k < 32; k += 2) {
                a0 += wcm[k*45+q]*wem[k*45+r];
                a1 += wcm[(k+1)*45+q]*wem[(k+1)*45+r];
            }
            d_G2[g] = a0 + a1;
        }
    }
}

// ============================ k0b: class kernels + mix matrices (49 blocks) ============================
__global__ __launch_bounds__(256) void k0b(const float* __restrict__ W2)
{
    int tid = threadIdx.x;
    int bid = blockIdx.x;
    if (bid < 45) {
        __shared__ float G2s[45*45];
        for (int t = tid; t < 45*45; t += 256) G2s[t] = d_G2[t];
        __syncthreads();
        if (tid >= 225) return;
        int cls = bid;
        int zc = cls / 9, yc = (cls % 9) / 3, xc = cls % 3;
        int s = tid;
        int sz = s / 25, sy = (s % 25) / 5, sx = s % 5;
        float acc = 0.f;
        for (int qz = 0; qz < 5; qz++) {
            if (!inQz(zc, qz)) continue;
            int rz = sz - qz; if (rz < 0 || rz > 4) continue;
            for (int qy = 0; qy < 3; qy++) {
                if (!inQ3(yc, qy)) continue;
                int ry = sy - qy; if (ry < 0 || ry > 2) continue;
                for (int qx = 0; qx < 3; qx++) {
                    if (!inQ3(xc, qx)) continue;
                    int rx = sx - qx; if (rx < 0 || rx > 2) continue;
                    acc += G2s[(qz*9+qy*3+qx)*45 + rz*9+ry*3+rx];
                }
            }
        }
        d_gcls[cls*225 + s] = acc;
    } else {
        int p = bid - 45;
        float r0 = d_r2p[p][0], r1 = d_r2p[p][1], r2 = d_r2p[p][2], r3 = d_r2p[p][3];
        for (int ij = tid; ij < 961; ij += 256)
            d_Mp[p*961 + ij] = r0*W2[ij] + r1*W2[961+ij] + r2*W2[2*961+ij] + r3*W2[3*961+ij];
    }
}

// ============================ fused: bilinear + exact conv + residual + mix ============================
#define TROWS 12
#define TS (TROWS*36)
#define TILE_F (CC*TS)
#define WCLS_F (4*5*225)
#define MROW   32                    // padded mix-matrix row (16B-aligned float4 reads)
#define MPS_F  (4*31*MROW)
#define SMEM_F (TILE_F + WCLS_F + MPS_F + 8)

__global__ __launch_bounds__(256, 2) void kfused(const float* __restrict__ x,
                                                 float* __restrict__ out)
{
    extern __shared__ float sm[];
    float* tile = sm;                       // [d][yy][xx] = d*432 + yy*36 + xx
    float* wcls = sm + TILE_F;              // [slot][zc*225 + s]
    float* Mps  = sm + TILE_F + WCLS_F;     // [p][31][MROW] padded
    float* offs = Mps + MPS_F;              // [p][2]

    int tx = threadIdx.x, ty = threadIdx.y;
    int tid = ty*32 + tx;
    int gx0 = blockIdx.x*32 - 2, gy0 = blockIdx.y*8 - 2;

    if (tid < 8) offs[tid] = ((const float*)d_offp)[tid];
    int oylo = blockIdx.y*8, oyhi = oylo + 7;
    int oxlo = blockIdx.x*32, oxhi = oxlo + 31;
    int yec = (oylo == 0) ? 1 : ((oyhi >= HO-1) ? 2 : 0);
    int xec = (oxlo == 0) ? 1 : ((oxhi >= WO-1) ? 2 : 0);

    for (int t = tid; t < WCLS_F; t += 256) {
        int slot = t / 1125, r = t % 1125;
        int ys = (slot & 1) ? yec : 0;
        int xs = (slot & 2) ? xec : 0;
        int zc = r / 225;
        wcls[t] = d_gcls[((zc*3 + ys)*3 + xs)*225 + (r % 225)];
    }
    // mix matrices: padded rows of MROW, zero in pad column
    for (int t = tid; t < MPS_F; t += 256) {
        int p = t / (31*MROW), r = t % (31*MROW);
        int ii = r / MROW, jj = r % MROW;
        Mps[t] = (jj < 31) ? d_Mp[p*961 + ii*31 + jj] : 0.f;
    }
    __syncthreads();   // offs ready before bilinear uses it

    // ---- bilinear halo tile from x ----
    for (int t = tid; t < TROWS*36; t += 256) {
        int yy = t / 36, xx = t % 36;
        int gy = gy0 + yy, gx = gx0 + xx;
        if (gy < 0 || gy >= HO || gx < 0 || gx >= WO) {
            #pragma unroll 4
            for (int c = 0; c < CC; c++) tile[c*TS + t] = 0.f;
        } else {
            int p = ((gy & 1) << 1) | (gx & 1);
            float ix = (gx + 0.5f)*0.5f - 0.5f + offs[p*2+0];
            float iy = (gy + 0.5f)*0.5f - 0.5f + offs[p*2+1];
            float x0f = floorf(ix), y0f = floorf(iy);
            float wx1 = ix - x0f, wy1 = iy - y0f;
            int x0 = (int)x0f, y0 = (int)y0f;
            float vx0 = (x0   >= 0 && x0   <= WI-1) ? 1.f : 0.f;
            float vx1 = (x0+1 >= 0 && x0+1 <= WI-1) ? 1.f : 0.f;
            float vy0 = (y0   >= 0 && y0   <= HI-1) ? 1.f : 0.f;
            float vy1 = (y0+1 >= 0 && y0+1 <= HI-1) ? 1.f : 0.f;
            int xi0 = min(max(x0,   0), WI-1), xi1 = min(max(x0+1, 0), WI-1);
            int yi0 = min(max(y0,   0), HI-1), yi1 = min(max(y0+1, 0), HI-1);
            float w00 = (1.f-wy1)*(1.f-wx1)*vy0*vx0;
            float w01 = (1.f-wy1)*wx1*vy0*vx1;
            float w10 = wy1*(1.f-wx1)*vy1*vx0;
            float w11 = wy1*wx1*vy1*vx1;
            int b00 = yi0*WI + xi0, b01 = yi0*WI + xi1;
            int b10 = yi1*WI + xi0, b11 = yi1*WI + xi1;
            #pragma unroll 4
            for (int c = 0; c < CC; c++) {
                const float* xc = x + c*(HI*WI);
                tile[c*TS + t] = w00*__ldg(xc+b00) + w01*__ldg(xc+b01)
                               + w10*__ldg(xc+b10) + w11*__ldg(xc+b11);
            }
        }
    }
    __syncthreads();

    int oy = blockIdx.y*8 + ty, ox = blockIdx.x*32 + tx;

    int yfl = (oy == 0 || oy == HO-1) ? 1 : 0;
    int xfl = (ox == 0 || ox == WO-1) ? 1 : 0;
    const float* gY = wcls + (yfl + 2*xfl)*1125;

    float acc[32];
    const float* ctr = tile + (ty+2)*36 + (tx+2);
    #pragma unroll
    for (int d = 0; d < CC; d++) acc[d] = ctr[d*TS];   // residual (+fea)
    acc[31] = 0.f;                                      // pad for float4 mix

    #pragma unroll 1
    for (int sy = 0; sy < 5; sy++) {
        #pragma unroll 1
        for (int sx = 0; sx < 5; sx++) {
            int t0 = sy*5 + sx;
            const float* tp = tile + (ty+sy)*36 + (tx+sx);
            float v[CC];
            #pragma unroll
            for (int d = 0; d < CC; d++) v[d] = tp[d*TS];

            // interior depths d=2..28 (zc=2)
            #pragma unroll
            for (int sz = 0; sz < 9; sz++) {
                float gv = gY[2*225 + sz*25 + t0];
                #pragma unroll
                for (int d = 2; d <= 28; d++) {
                    int src = d + sz - 4;
                    if (src >= 0 && src < CC) acc[d] += gv * v[src];
                }
            }
            #pragma unroll
            for (int sz = 4; sz < 9; sz++)
                acc[0] += gY[0*225 + sz*25 + t0] * v[sz-4];
            #pragma unroll
            for (int sz = 3; sz < 9; sz++)
                acc[1] += gY[1*225 + sz*25 + t0] * v[sz-3];
            #pragma unroll
            for (int sz = 0; sz < 6; sz++)
                acc[29] += gY[3*225 + sz*25 + t0] * v[25+sz];
            #pragma unroll
            for (int sz = 0; sz < 5; sz++)
                acc[30] += gY[4*225 + sz*25 + t0] * v[26+sz];
        }
    }

    // ---- per-pixel channel mix + fea0 (float4 reads of padded M rows) ----
    const float* M = Mps + (((oy & 1) << 1) | (ox & 1))*(31*MROW);
    int pix = oy*WO + ox;
    #pragma unroll 1
    for (int ii = 0; ii < 30; ii += 2) {
        const float* M0 = M + ii*MROW;
        const float* M1 = M0 + MROW;
        float s00 = 0.f, s01 = 0.f, s10 = 0.f, s11 = 0.f;
        #pragma unroll
        for (int jc = 0; jc < 8; jc += 2) {
            float4 a0 = *(const float4*)(M0 + jc*4);
            float4 b0 = *(const float4*)(M0 + jc*4 + 4);
            float4 a1 = *(const float4*)(M1 + jc*4);
            float4 b1 = *(const float4*)(M1 + jc*4 + 4);
            int j0 = jc*4;
            s00 += a0.x*acc[j0+0] + a0.y*acc[j0+1] + a0.z*acc[j0+2] + a0.w*acc[j0+3];
            s01 += b0.x*acc[j0+4] + b0.y*acc[j0+5] + b0.z*acc[j0+6] + b0.w*acc[j0+7];
            s10 += a1.x*acc[j0+0] + a1.y*acc[j0+1] + a1.z*acc[j0+2] + a1.w*acc[j0+3];
            s11 += b1.x*acc[j0+4] + b1.y*acc[j0+5] + b1.z*acc[j0+6] + b1.w*acc[j0+7];
        }
        out[ii*NPIX + pix]     = ctr[ii*TS]     + (s00 + s01);
        out[(ii+1)*NPIX + pix] = ctr[(ii+1)*TS] + (s10 + s11);
    }
    {   // ii = 30 tail
        const float* M0 = M + 30*MROW;
        float s0 = 0.f, s1 = 0.f;
        #pragma unroll
        for (int jc = 0; jc < 8; jc += 2) {
            float4 a0 = *(const float4*)(M0 + jc*4);
            float4 b0 = *(const float4*)(M0 + jc*4 + 4);
            int j0 = jc*4;
            s0 += a0.x*acc[j0+0] + a0.y*acc[j0+1] + a0.z*acc[j0+2] + a0.w*acc[j0+3];
            s1 += b0.x*acc[j0+4] + b0.y*acc[j0+5] + b0.z*acc[j0+6] + b0.w*acc[j0+7];
        }
        out[30*NPIX + pix] = ctr[30*TS] + (s0 + s1);
    }
}

// ============================ launch ============================
extern "C" void kernel_launch(void* const* d_in, const int* in_sizes, int n_in,
                              void* d_out, int out_size)
{
    const float* x   = (const float*)d_in[0];
    // d_in[1] = scale (always 2; parity tables assume it)
    const float* WE  = (const float*)d_in[2];
    const float* WC  = (const float*)d_in[3];
    const float* W2  = (const float*)d_in[4];
    const float* bw1 = (const float*)d_in[5];
    const float* bb1 = (const float*)d_in[6];
    const float* bw2 = (const float*)d_in[7];
    const float* bb2 = (const float*)d_in[8];
    const float* r2w = (const float*)d_in[9];
    const float* r2b = (const float*)d_in[10];
    const float* ow  = (const float*)d_in[11];
    const float* ob  = (const float*)d_in[12];
    const float* l1w = (const float*)d_in[13];
    const float* l1b = (const float*)d_in[14];
    const float* l2w = (const float*)d_in[15];
    const float* l2b = (const float*)d_in[16];
    float* out = (float*)d_out;

    static int smem_set = 0;
    if (!smem_set) {
        cudaFuncSetAttribute(kfused, cudaFuncAttributeMaxDynamicSharedMemorySize,
                             SMEM_F * (int)sizeof(float));
        smem_set = 1;
    }

    k0a<<<148, 256>>>(WE, WC, bw1, bb1, bw2, bb2,
                      r2w, r2b, ow, ob, l1w, l1b, l2w, l2b);
    k0b<<<49, 256>>>(W2);
    kfused<<<dim3(WO/32, HO/8), dim3(32, 8), SMEM_F*(int)sizeof(float)>>>(x, out);
}